// round 12
// baseline (speedup 1.0000x reference)
#include <cuda_runtime.h>
#include <cuda_fp16.h>
#include <math.h>
#include <stdint.h>

#define MAXN 16
#define HDIM 64
#define DDIM 64
#define HID 40
#define BMAX 65536

// ---------------- device scratch (no allocations allowed) ----------------
__device__ int g_n[BMAX];                  // per-row argmax

// ---------------- helpers ----------------
// 1-MUFU gelu: hardware tanh.approx.f32
__device__ __forceinline__ float gelu_t(float x) {
    float x2 = x * x;
    float u = x * (0.7978845608f + 0.0356774081f * x2);
    float t;
    asm("tanh.approx.f32 %0, %1;" : "=f"(t) : "f"(u));
    return 0.5f * x * (1.0f + t);
}
// half2 "2x gelu": G = x*(1+tanh(u)); pair with 0.5-scaled W2
__device__ __forceinline__ uint32_t gelu2_h2(uint32_t xb, __half2 A2, __half2 B2) {
    __half2 x = *reinterpret_cast<__half2*>(&xb);
    __half2 x2 = __hmul2(x, x);
    __half2 u = __hmul2(x, __hfma2(B2, x2, A2));
    uint32_t ub = *reinterpret_cast<uint32_t*>(&u);
    uint32_t tb;
    asm("tanh.approx.f16x2 %0, %1;" : "=r"(tb) : "r"(ub));
    __half2 t = *reinterpret_cast<__half2*>(&tb);
    __half2 y = __hfma2(x, t, x);
    return *reinterpret_cast<uint32_t*>(&y);
}
// pack two floats -> half2 bits (lo in low 16 bits)
__device__ __forceinline__ uint32_t f2h2(float lo, float hi) {
    uint32_t r;
    asm("cvt.rn.f16x2.f32 %0, %1, %2;" : "=r"(r) : "f"(hi), "f"(lo));
    return r;
}
__device__ __forceinline__ void mma_f16(float& c0, float& c1, float& c2, float& c3,
                                        uint32_t a0, uint32_t a1, uint32_t a2, uint32_t a3,
                                        uint32_t b0, uint32_t b1) {
    asm volatile(
        "mma.sync.aligned.m16n8k16.row.col.f32.f16.f16.f32 "
        "{%0,%1,%2,%3}, {%4,%5,%6,%7}, {%8,%9}, {%0,%1,%2,%3};"
        : "+f"(c0), "+f"(c1), "+f"(c2), "+f"(c3)
        : "r"(a0), "r"(a1), "r"(a2), "r"(a3), "r"(b0), "r"(b1));
}

// ================= sp: size MLP + argmax + mask/batch/n_pred =================
#define SP_ROWS 128
__global__ void __launch_bounds__(SP_ROWS) sp_kernel(
    const float* __restrict__ z,
    const float* __restrict__ w1, const float* __restrict__ b1,
    const float* __restrict__ w2, const float* __restrict__ b2,
    float* __restrict__ out_npred, float* __restrict__ out_mask,
    float* __restrict__ out_batch) {
    __shared__ float zs[SP_ROWS][65];
    __shared__ float w1s[HDIM * HID];
    __shared__ float w2s[HID * MAXN];
    __shared__ float b1s[HID];
    __shared__ float b2s[MAXN];

    int tid = threadIdx.x;
    int row0 = blockIdx.x * SP_ROWS;

    for (int i = tid; i < HDIM * HID; i += SP_ROWS) w1s[i] = w1[i];
    for (int i = tid; i < HID * MAXN; i += SP_ROWS) w2s[i] = w2[i];
    if (tid < HID)  b1s[tid] = b1[tid];
    if (tid < MAXN) b2s[tid] = b2[tid];
    for (int i = tid; i < SP_ROWS * (HDIM / 4); i += SP_ROWS) {
        int r = i / (HDIM / 4), c4 = i % (HDIM / 4);
        float4 v = ((const float4*)(z + (size_t)(row0 + r) * HDIM))[c4];
        zs[r][c4 * 4 + 0] = v.x;
        zs[r][c4 * 4 + 1] = v.y;
        zs[r][c4 * 4 + 2] = v.z;
        zs[r][c4 * 4 + 3] = v.w;
    }
    __syncthreads();

    int b = row0 + tid;
    float h[HID];
    #pragma unroll
    for (int j4 = 0; j4 < HID / 4; j4++) {
        float4 bv = *(const float4*)&b1s[j4 * 4];
        h[j4 * 4 + 0] = bv.x; h[j4 * 4 + 1] = bv.y;
        h[j4 * 4 + 2] = bv.z; h[j4 * 4 + 3] = bv.w;
    }
    for (int k = 0; k < HDIM; k++) {
        float zk = zs[tid][k];
        const float4* wr = (const float4*)&w1s[k * HID];
        #pragma unroll
        for (int j4 = 0; j4 < HID / 4; j4++) {
            float4 w = wr[j4];
            h[j4 * 4 + 0] += zk * w.x;
            h[j4 * 4 + 1] += zk * w.y;
            h[j4 * 4 + 2] += zk * w.z;
            h[j4 * 4 + 3] += zk * w.w;
        }
    }
    float o[MAXN];
    #pragma unroll
    for (int p4 = 0; p4 < MAXN / 4; p4++) {
        float4 bv = *(const float4*)&b2s[p4 * 4];
        o[p4 * 4 + 0] = bv.x; o[p4 * 4 + 1] = bv.y;
        o[p4 * 4 + 2] = bv.z; o[p4 * 4 + 3] = bv.w;
    }
    #pragma unroll
    for (int j = 0; j < HID; j++) {
        float hj = gelu_t(h[j]);
        const float4* wr = (const float4*)&w2s[j * MAXN];
        #pragma unroll
        for (int p4 = 0; p4 < MAXN / 4; p4++) {
            float4 w = wr[p4];
            o[p4 * 4 + 0] += hj * w.x;
            o[p4 * 4 + 1] += hj * w.y;
            o[p4 * 4 + 2] += hj * w.z;
            o[p4 * 4 + 3] += hj * w.w;
        }
    }
    int n = 0; float best = o[0];
    #pragma unroll
    for (int p = 1; p < MAXN; p++)
        if (o[p] > best) { best = o[p]; n = p; }
    g_n[b] = n;

    size_t base = (size_t)b * MAXN;
    #pragma unroll
    for (int p4 = 0; p4 < MAXN / 4; p4++)
        *(float4*)(out_npred + base + p4 * 4) =
            make_float4(o[p4 * 4 + 0], o[p4 * 4 + 1], o[p4 * 4 + 2], o[p4 * 4 + 3]);
    float fb = (float)b;
    #pragma unroll
    for (int p4 = 0; p4 < MAXN / 4; p4++) {
        float4 mv;
        mv.x = (p4 * 4 + 0 < n) ? 1.0f : 0.0f;
        mv.y = (p4 * 4 + 1 < n) ? 1.0f : 0.0f;
        mv.z = (p4 * 4 + 2 < n) ? 1.0f : 0.0f;
        mv.w = (p4 * 4 + 3 < n) ? 1.0f : 0.0f;
        *(float4*)(out_mask + base + p4 * 4) = mv;
        *(float4*)(out_batch + base + p4 * 4) = make_float4(fb, fb, fb, fb);
    }
}

// ================= dec: persistent fp16-MMA, reg H handoff, STG.128 epilogue ======
#define DEC_THREADS 256
// dynamic smem layout (float indices)
#define SOFF_PE  0                        // [16][68] fp32 = 1088
#define SOFF_ZB  (SOFF_PE + 16 * 68)      // 8 warps * 128 = 1024 (init scratch too)
#define SOFF_B1  (SOFF_ZB + 1024)         // 64
#define SOFF_B2  (SOFF_B1 + 64)           // 64 (PERMUTED b2)
#define SOFF_W1F (SOFF_B2 + 64)           // 2048 u32: W1 frags [kit*8+nt][lane]
#define SOFF_W2F (SOFF_W1F + 2048)        // 2048 u32 (PERMUTED cols, 0.5-scaled)
#define DEC_SMEM_FLOATS (SOFF_W2F + 2048)
#define DEC_SMEM_BYTES  (DEC_SMEM_FLOATS * 4)

__global__ void __launch_bounds__(DEC_THREADS, 2) dec_kernel(
    const float* __restrict__ z,
    const float* __restrict__ dw1, const float* __restrict__ db1,
    const float* __restrict__ dw2, const float* __restrict__ db2,
    const float* __restrict__ pw1, const float* __restrict__ pb1,
    const float* __restrict__ pw2, const float* __restrict__ pb2,
    float* __restrict__ out_x, int nstrips) {
    extern __shared__ __align__(16) float smem[];
    float* pe_f = smem + SOFF_PE;          // fp32, pitch 68
    float* zb   = smem + SOFF_ZB;
    float* b1s  = smem + SOFF_B1;
    float* b2p  = smem + SOFF_B2;          // permuted
    uint32_t* W1f = (uint32_t*)(smem + SOFF_W1F);
    uint32_t* W2f = (uint32_t*)(smem + SOFF_W2F);

    int tid = threadIdx.x;
    int wid = tid >> 5;
    int lane = tid & 31;
    int grp = lane >> 2;                   // 0..7
    int rem = lane & 3;                    // 0..3

    // ---- one-time prologue ----
    {
        float* hid = zb;                   // init scratch (640 <= 1024)
        for (int i = tid; i < MAXN * HID; i += DEC_THREADS)
            hid[i] = gelu_t(pw1[i] + pb1[i % HID]);
        if (tid < 64) {
            b1s[tid] = db1[tid];
            // b2 permuted: b2p[j] = b2[f(j)], f(j)=16*((j&7)>>1)+2*(j>>3)+(j&1)
            int fc = 16 * ((tid & 7) >> 1) + 2 * (tid >> 3) + (tid & 1);
            b2p[tid] = db2[fc];
        }
        __syncthreads();
        for (int i = tid; i < MAXN * 64; i += DEC_THREADS) {
            int p = i >> 6, d = i & 63;
            float acc = pb2[d];
            #pragma unroll
            for (int j = 0; j < HID; j++) acc += hid[p * HID + j] * pw2[j * 64 + d];
            pe_f[p * 68 + d] = acc;
        }
        __syncthreads();   // hid scratch done before zb reuse
        for (int i = tid; i < 2048; i += DEC_THREADS) {
            int sel = i & 1;
            int lane_ = (i >> 1) & 31;
            int ntk = i >> 6;              // kit*8+nt
            int kit = ntk >> 3, nt = ntk & 7;
            int g_ = lane_ >> 2, r_ = lane_ & 3;
            int k = kit * 16 + 2 * r_ + sel * 8;
            int n = nt * 8 + g_;
            W1f[i] = f2h2(dw1[k * 64 + n], dw1[(k + 1) * 64 + n]);
            int fc = 16 * ((n & 7) >> 1) + 2 * (n >> 3) + (n & 1);
            // 0.5-scaled W2: pairs with G = 2*gelu from epilogue1
            W2f[i] = f2h2(0.5f * dw2[k * 64 + fc], 0.5f * dw2[(k + 1) * 64 + fc]);
        }
    }
    __syncthreads();

    const __half2 A2 = __float2half2_rn(0.7978845608f);
    const __half2 B2 = __float2half2_rn(0.0356774081f);

    float* zw = zb + wid * 128;

    int stride = gridDim.x * 8;
    int s = blockIdx.x * 8 + wid;
    if (s >= nstrips) return;

    float4 zcur = ((const float4*)(z + (size_t)s * 128))[lane];
    int ncur0 = g_n[2 * s], ncur1 = g_n[2 * s + 1];

    for (; s < nstrips; s += stride) {
        *(float4*)&zw[lane * 4] = zcur;
        int n0 = ncur0, n1 = ncur1;
        __syncwarp();

        int snext = s + stride;
        if (snext < nstrips) {
            zcur = ((const float4*)(z + (size_t)snext * 128))[lane];
            ncur0 = g_n[2 * snext];
            ncur1 = g_n[2 * snext + 1];
        }

        float C[2][8][4];
        // ---- init C with b1 ----
        #pragma unroll
        for (int nt = 0; nt < 8; nt++) {
            float2 bv = *(const float2*)&b1s[nt * 8 + 2 * rem];
            #pragma unroll
            for (int mt = 0; mt < 2; mt++) {
                C[mt][nt][0] = bv.x; C[mt][nt][1] = bv.y;
                C[mt][nt][2] = bv.x; C[mt][nt][3] = bv.y;
            }
        }

        // ---- GEMM1: A inline (z x pe fp32 -> h2), W1 frags LDS.64 ----
        #pragma unroll
        for (int kit = 0; kit < 4; kit++) {
            int kk = kit * 16 + 2 * rem;
            uint2 bf[8];
            #pragma unroll
            for (int nt = 0; nt < 8; nt++)
                bf[nt] = *(const uint2*)&W1f[(((kit << 3) + nt) << 6) + (lane << 1)];
            float2 p0lo = *(const float2*)&pe_f[grp * 68 + kk];
            float2 p1lo = *(const float2*)&pe_f[(grp + 8) * 68 + kk];
            float2 p0hi = *(const float2*)&pe_f[grp * 68 + kk + 8];
            float2 p1hi = *(const float2*)&pe_f[(grp + 8) * 68 + kk + 8];
            #pragma unroll
            for (int mt = 0; mt < 2; mt++) {
                float2 zlo = *(const float2*)&zw[mt * 64 + kk];
                float2 zhi = *(const float2*)&zw[mt * 64 + kk + 8];
                uint32_t a0 = f2h2(zlo.x * p0lo.x, zlo.y * p0lo.y);
                uint32_t a1 = f2h2(zlo.x * p1lo.x, zlo.y * p1lo.y);
                uint32_t a2 = f2h2(zhi.x * p0hi.x, zhi.y * p0hi.y);
                uint32_t a3 = f2h2(zhi.x * p1hi.x, zhi.y * p1hi.y);
                #pragma unroll
                for (int nt = 0; nt < 8; nt++)
                    mma_f16(C[mt][nt][0], C[mt][nt][1], C[mt][nt][2], C[mt][nt][3],
                            a0, a1, a2, a3, bf[nt].x, bf[nt].y);
            }
        }

        // ---- epilogue1: half2 2x-gelu -> H fragments in registers ----
        uint32_t Hf[2][4][4];
        #pragma unroll
        for (int mt = 0; mt < 2; mt++) {
            #pragma unroll
            for (int kit = 0; kit < 4; kit++) {
                int na = 2 * kit, nb = 2 * kit + 1;
                Hf[mt][kit][0] = gelu2_h2(f2h2(C[mt][na][0], C[mt][na][1]), A2, B2);
                Hf[mt][kit][1] = gelu2_h2(f2h2(C[mt][na][2], C[mt][na][3]), A2, B2);
                Hf[mt][kit][2] = gelu2_h2(f2h2(C[mt][nb][0], C[mt][nb][1]), A2, B2);
                Hf[mt][kit][3] = gelu2_h2(f2h2(C[mt][nb][2], C[mt][nb][3]), A2, B2);
            }
        }

        // ---- re-init C with permuted b2 ----
        #pragma unroll
        for (int nt = 0; nt < 8; nt++) {
            float2 bv = *(const float2*)&b2p[nt * 8 + 2 * rem];
            #pragma unroll
            for (int mt = 0; mt < 2; mt++) {
                C[mt][nt][0] = bv.x; C[mt][nt][1] = bv.y;
                C[mt][nt][2] = bv.x; C[mt][nt][3] = bv.y;
            }
        }

        // ---- GEMM2: H (=2*gelu) from registers, 0.5*W2 frags ----
        #pragma unroll
        for (int kit = 0; kit < 4; kit++) {
            uint2 bf[8];
            #pragma unroll
            for (int nt = 0; nt < 8; nt++)
                bf[nt] = *(const uint2*)&W2f[(((kit << 3) + nt) << 6) + (lane << 1)];
            #pragma unroll
            for (int mt = 0; mt < 2; mt++) {
                #pragma unroll
                for (int nt = 0; nt < 8; nt++)
                    mma_f16(C[mt][nt][0], C[mt][nt][1], C[mt][nt][2], C[mt][nt][3],
                            Hf[mt][kit][0], Hf[mt][kit][1],
                            Hf[mt][kit][2], Hf[mt][kit][3],
                            bf[nt].x, bf[nt].y);
            }
        }

        // ---- epilogue2: thread owns cols [16rem,16rem+16) -> 4x STG.128 per row ----
        #pragma unroll
        for (int mt = 0; mt < 2; mt++) {
            int nm = mt ? n1 : n0;
            bool v0 = grp < nm;
            bool v1 = grp + 8 < nm;
            int r0 = mt * 16 + grp;
            float* orow0 = out_x + ((size_t)s * 32 + r0) * DDIM + 16 * rem;
            float* orow1 = orow0 + 8 * DDIM;
            #pragma unroll
            for (int t = 0; t < 4; t++) {
                int na = 2 * t, nb = 2 * t + 1;
                float4 lo, hi;
                lo.x = v0 ? C[mt][na][0] : 0.0f;
                lo.y = v0 ? C[mt][na][1] : 0.0f;
                lo.z = v0 ? C[mt][nb][0] : 0.0f;
                lo.w = v0 ? C[mt][nb][1] : 0.0f;
                hi.x = v1 ? C[mt][na][2] : 0.0f;
                hi.y = v1 ? C[mt][na][3] : 0.0f;
                hi.z = v1 ? C[mt][nb][2] : 0.0f;
                hi.w = v1 ? C[mt][nb][3] : 0.0f;
                *(float4*)(orow0 + 4 * t) = lo;
                *(float4*)(orow1 + 4 * t) = hi;
            }
        }
        __syncwarp();
    }
}

// ================= launch =================
extern "C" void kernel_launch(void* const* d_in, const int* in_sizes, int n_in,
                              void* d_out, int out_size) {
    const float* z      = (const float*)d_in[0];
    const float* sp_w1  = (const float*)d_in[1];
    const float* sp_b1  = (const float*)d_in[2];
    const float* sp_w2  = (const float*)d_in[3];
    const float* sp_b2  = (const float*)d_in[4];
    const float* pe_w1  = (const float*)d_in[5];
    const float* pe_b1  = (const float*)d_in[6];
    const float* pe_w2  = (const float*)d_in[7];
    const float* pe_b2  = (const float*)d_in[8];
    const float* dec_w1 = (const float*)d_in[9];
    const float* dec_b1 = (const float*)d_in[10];
    const float* dec_w2 = (const float*)d_in[11];
    const float* dec_b2 = (const float*)d_in[12];

    int B = in_sizes[0] / HDIM;   // 65536

    float* out = (float*)d_out;
    float* out_x     = out;                               // [B,16,64]
    float* out_mask  = out_x + (size_t)B * MAXN * DDIM;   // [B,16]
    float* out_batch = out_mask + (size_t)B * MAXN;       // [B,16]
    float* out_npred = out_batch + (size_t)B * MAXN;      // [B,16]

    static int nsm = 0;
    if (!nsm) {
        cudaDeviceGetAttribute(&nsm, cudaDevAttrMultiProcessorCount, 0);
        if (nsm <= 0) nsm = 148;
        cudaFuncSetAttribute(dec_kernel, cudaFuncAttributeMaxDynamicSharedMemorySize,
                             DEC_SMEM_BYTES);
    }

    sp_kernel<<<B / SP_ROWS, SP_ROWS>>>(z, sp_w1, sp_b1, sp_w2, sp_b2,
                                        out_npred, out_mask, out_batch);

    int nstrips = B / 2;   // 32768 strips of 32 rows
    dec_kernel<<<nsm * 2, DEC_THREADS, DEC_SMEM_BYTES>>>(
        z, dec_w1, dec_b1, dec_w2, dec_b2,
        pe_w1, pe_b1, pe_w2, pe_b2, out_x, nstrips);
}

// round 13
// speedup vs baseline: 1.0600x; 1.0600x over previous
#include <cuda_runtime.h>
#include <cuda_fp16.h>
#include <math.h>
#include <stdint.h>

#define MAXN 16
#define HDIM 64
#define DDIM 64
#define HID 40
#define BMAX 65536

// ---------------- device scratch (no allocations allowed) ----------------
__device__ int g_n[BMAX];                  // per-row argmax

// ---------------- helpers ----------------
// 1-MUFU gelu: hardware tanh.approx.f32
__device__ __forceinline__ float gelu_t(float x) {
    float x2 = x * x;
    float u = x * (0.7978845608f + 0.0356774081f * x2);
    float t;
    asm("tanh.approx.f32 %0, %1;" : "=f"(t) : "f"(u));
    return 0.5f * x * (1.0f + t);
}
// pack two floats -> half2 bits (lo in low 16 bits)
__device__ __forceinline__ uint32_t f2h2(float lo, float hi) {
    uint32_t r;
    asm("cvt.rn.f16x2.f32 %0, %1, %2;" : "=r"(r) : "f"(hi), "f"(lo));
    return r;
}
__device__ __forceinline__ void mma_f16(float& c0, float& c1, float& c2, float& c3,
                                        uint32_t a0, uint32_t a1, uint32_t a2, uint32_t a3,
                                        uint32_t b0, uint32_t b1) {
    asm volatile(
        "mma.sync.aligned.m16n8k16.row.col.f32.f16.f16.f32 "
        "{%0,%1,%2,%3}, {%4,%5,%6,%7}, {%8,%9}, {%0,%1,%2,%3};"
        : "+f"(c0), "+f"(c1), "+f"(c2), "+f"(c3)
        : "r"(a0), "r"(a1), "r"(a2), "r"(a3), "r"(b0), "r"(b1));
}

// ================= sp: size MLP + argmax + mask/batch/n_pred =================
#define SP_ROWS 128
__global__ void __launch_bounds__(SP_ROWS) sp_kernel(
    const float* __restrict__ z,
    const float* __restrict__ w1, const float* __restrict__ b1,
    const float* __restrict__ w2, const float* __restrict__ b2,
    float* __restrict__ out_npred, float* __restrict__ out_mask,
    float* __restrict__ out_batch) {
    __shared__ float zs[SP_ROWS][65];
    __shared__ float w1s[HDIM * HID];
    __shared__ float w2s[HID * MAXN];
    __shared__ float b1s[HID];
    __shared__ float b2s[MAXN];

    int tid = threadIdx.x;
    int row0 = blockIdx.x * SP_ROWS;

    for (int i = tid; i < HDIM * HID; i += SP_ROWS) w1s[i] = w1[i];
    for (int i = tid; i < HID * MAXN; i += SP_ROWS) w2s[i] = w2[i];
    if (tid < HID)  b1s[tid] = b1[tid];
    if (tid < MAXN) b2s[tid] = b2[tid];
    for (int i = tid; i < SP_ROWS * (HDIM / 4); i += SP_ROWS) {
        int r = i / (HDIM / 4), c4 = i % (HDIM / 4);
        float4 v = ((const float4*)(z + (size_t)(row0 + r) * HDIM))[c4];
        zs[r][c4 * 4 + 0] = v.x;
        zs[r][c4 * 4 + 1] = v.y;
        zs[r][c4 * 4 + 2] = v.z;
        zs[r][c4 * 4 + 3] = v.w;
    }
    __syncthreads();

    int b = row0 + tid;
    float h[HID];
    #pragma unroll
    for (int j4 = 0; j4 < HID / 4; j4++) {
        float4 bv = *(const float4*)&b1s[j4 * 4];
        h[j4 * 4 + 0] = bv.x; h[j4 * 4 + 1] = bv.y;
        h[j4 * 4 + 2] = bv.z; h[j4 * 4 + 3] = bv.w;
    }
    for (int k = 0; k < HDIM; k++) {
        float zk = zs[tid][k];
        const float4* wr = (const float4*)&w1s[k * HID];
        #pragma unroll
        for (int j4 = 0; j4 < HID / 4; j4++) {
            float4 w = wr[j4];
            h[j4 * 4 + 0] += zk * w.x;
            h[j4 * 4 + 1] += zk * w.y;
            h[j4 * 4 + 2] += zk * w.z;
            h[j4 * 4 + 3] += zk * w.w;
        }
    }
    float o[MAXN];
    #pragma unroll
    for (int p4 = 0; p4 < MAXN / 4; p4++) {
        float4 bv = *(const float4*)&b2s[p4 * 4];
        o[p4 * 4 + 0] = bv.x; o[p4 * 4 + 1] = bv.y;
        o[p4 * 4 + 2] = bv.z; o[p4 * 4 + 3] = bv.w;
    }
    #pragma unroll
    for (int j = 0; j < HID; j++) {
        float hj = gelu_t(h[j]);
        const float4* wr = (const float4*)&w2s[j * MAXN];
        #pragma unroll
        for (int p4 = 0; p4 < MAXN / 4; p4++) {
            float4 w = wr[p4];
            o[p4 * 4 + 0] += hj * w.x;
            o[p4 * 4 + 1] += hj * w.y;
            o[p4 * 4 + 2] += hj * w.z;
            o[p4 * 4 + 3] += hj * w.w;
        }
    }
    int n = 0; float best = o[0];
    #pragma unroll
    for (int p = 1; p < MAXN; p++)
        if (o[p] > best) { best = o[p]; n = p; }
    g_n[b] = n;

    size_t base = (size_t)b * MAXN;
    #pragma unroll
    for (int p4 = 0; p4 < MAXN / 4; p4++)
        __stcs((float4*)(out_npred + base + p4 * 4),
               make_float4(o[p4 * 4 + 0], o[p4 * 4 + 1], o[p4 * 4 + 2], o[p4 * 4 + 3]));
    float fb = (float)b;
    #pragma unroll
    for (int p4 = 0; p4 < MAXN / 4; p4++) {
        float4 mv;
        mv.x = (p4 * 4 + 0 < n) ? 1.0f : 0.0f;
        mv.y = (p4 * 4 + 1 < n) ? 1.0f : 0.0f;
        mv.z = (p4 * 4 + 2 < n) ? 1.0f : 0.0f;
        mv.w = (p4 * 4 + 3 < n) ? 1.0f : 0.0f;
        __stcs((float4*)(out_mask + base + p4 * 4), mv);
        __stcs((float4*)(out_batch + base + p4 * 4), make_float4(fb, fb, fb, fb));
    }
}

// ================= dec: persistent fp16-MMA, reg H handoff (R10-best config) =====
#define DEC_THREADS 256
// dynamic smem layout (float indices)
#define SOFF_PE  0                        // [16][68] fp32 = 1088
#define SOFF_ZB  (SOFF_PE + 16 * 68)      // 8 warps * 128 = 1024 (init scratch too)
#define SOFF_B1  (SOFF_ZB + 1024)         // 64
#define SOFF_B2  (SOFF_B1 + 64)           // 64
#define SOFF_W1F (SOFF_B2 + 64)           // 2048 u32: W1 frags [kit*8+nt][lane]
#define SOFF_W2F (SOFF_W1F + 2048)        // 2048 u32
#define DEC_SMEM_FLOATS (SOFF_W2F + 2048)
#define DEC_SMEM_BYTES  (DEC_SMEM_FLOATS * 4)

__global__ void __launch_bounds__(DEC_THREADS, 2) dec_kernel(
    const float* __restrict__ z,
    const float* __restrict__ dw1, const float* __restrict__ db1,
    const float* __restrict__ dw2, const float* __restrict__ db2,
    const float* __restrict__ pw1, const float* __restrict__ pb1,
    const float* __restrict__ pw2, const float* __restrict__ pb2,
    float* __restrict__ out_x, int nstrips) {
    extern __shared__ __align__(16) float smem[];
    float* pe_f = smem + SOFF_PE;          // fp32, pitch 68
    float* zb   = smem + SOFF_ZB;
    float* b1s  = smem + SOFF_B1;
    float* b2s  = smem + SOFF_B2;
    uint32_t* W1f = (uint32_t*)(smem + SOFF_W1F);
    uint32_t* W2f = (uint32_t*)(smem + SOFF_W2F);

    int tid = threadIdx.x;
    int wid = tid >> 5;
    int lane = tid & 31;
    int grp = lane >> 2;                   // 0..7
    int rem = lane & 3;                    // 0..3

    // ---- one-time prologue ----
    {
        float* hid = zb;                   // init scratch (640 <= 1024)
        for (int i = tid; i < MAXN * HID; i += DEC_THREADS)
            hid[i] = gelu_t(pw1[i] + pb1[i % HID]);
        if (tid < 64) { b1s[tid] = db1[tid]; b2s[tid] = db2[tid]; }
        __syncthreads();
        for (int i = tid; i < MAXN * 64; i += DEC_THREADS) {
            int p = i >> 6, d = i & 63;
            float acc = pb2[d];
            #pragma unroll
            for (int j = 0; j < HID; j++) acc += hid[p * HID + j] * pw2[j * 64 + d];
            pe_f[p * 68 + d] = acc;
        }
        __syncthreads();   // hid scratch done before zb reuse
        for (int i = tid; i < 2048; i += DEC_THREADS) {
            int sel = i & 1;
            int lane_ = (i >> 1) & 31;
            int ntk = i >> 6;              // kit*8+nt
            int kit = ntk >> 3, nt = ntk & 7;
            int g_ = lane_ >> 2, r_ = lane_ & 3;
            int k = kit * 16 + 2 * r_ + sel * 8;
            int n = nt * 8 + g_;
            W1f[i] = f2h2(dw1[k * 64 + n], dw1[(k + 1) * 64 + n]);
            W2f[i] = f2h2(dw2[k * 64 + n], dw2[(k + 1) * 64 + n]);
        }
    }
    __syncthreads();

    float* zw = zb + wid * 128;

    int stride = gridDim.x * 8;
    int s = blockIdx.x * 8 + wid;
    if (s >= nstrips) return;

    float4 zcur = ((const float4*)(z + (size_t)s * 128))[lane];
    int ncur0 = g_n[2 * s], ncur1 = g_n[2 * s + 1];

    for (; s < nstrips; s += stride) {
        *(float4*)&zw[lane * 4] = zcur;
        int n0 = ncur0, n1 = ncur1;
        __syncwarp();

        int snext = s + stride;
        if (snext < nstrips) {
            zcur = ((const float4*)(z + (size_t)snext * 128))[lane];
            ncur0 = g_n[2 * snext];
            ncur1 = g_n[2 * snext + 1];
        }

        float C[2][8][4];
        // ---- init C with b1 (bias folded into accumulation) ----
        #pragma unroll
        for (int nt = 0; nt < 8; nt++) {
            float2 bv = *(const float2*)&b1s[nt * 8 + 2 * rem];
            #pragma unroll
            for (int mt = 0; mt < 2; mt++) {
                C[mt][nt][0] = bv.x; C[mt][nt][1] = bv.y;
                C[mt][nt][2] = bv.x; C[mt][nt][3] = bv.y;
            }
        }

        // ---- GEMM1: A built inline (z smem x pe smem), W1 frags LDS.64 ----
        #pragma unroll
        for (int kit = 0; kit < 4; kit++) {
            int kk = kit * 16 + 2 * rem;
            uint2 bf[8];
            #pragma unroll
            for (int nt = 0; nt < 8; nt++)
                bf[nt] = *(const uint2*)&W1f[(((kit << 3) + nt) << 6) + (lane << 1)];
            float2 p0lo = *(const float2*)&pe_f[grp * 68 + kk];
            float2 p1lo = *(const float2*)&pe_f[(grp + 8) * 68 + kk];
            float2 p0hi = *(const float2*)&pe_f[grp * 68 + kk + 8];
            float2 p1hi = *(const float2*)&pe_f[(grp + 8) * 68 + kk + 8];
            #pragma unroll
            for (int mt = 0; mt < 2; mt++) {
                float2 zlo = *(const float2*)&zw[mt * 64 + kk];
                float2 zhi = *(const float2*)&zw[mt * 64 + kk + 8];
                uint32_t a0 = f2h2(zlo.x * p0lo.x, zlo.y * p0lo.y);
                uint32_t a1 = f2h2(zlo.x * p1lo.x, zlo.y * p1lo.y);
                uint32_t a2 = f2h2(zhi.x * p0hi.x, zhi.y * p0hi.y);
                uint32_t a3 = f2h2(zhi.x * p1hi.x, zhi.y * p1hi.y);
                #pragma unroll
                for (int nt = 0; nt < 8; nt++)
                    mma_f16(C[mt][nt][0], C[mt][nt][1], C[mt][nt][2], C[mt][nt][3],
                            a0, a1, a2, a3, bf[nt].x, bf[nt].y);
            }
        }

        // ---- epilogue1: gelu -> H fragments IN REGISTERS (C-layout == A-layout) ----
        uint32_t Hf[2][4][4];
        #pragma unroll
        for (int mt = 0; mt < 2; mt++) {
            #pragma unroll
            for (int kit = 0; kit < 4; kit++) {
                int na = 2 * kit, nb = 2 * kit + 1;
                Hf[mt][kit][0] = f2h2(gelu_t(C[mt][na][0]), gelu_t(C[mt][na][1]));
                Hf[mt][kit][1] = f2h2(gelu_t(C[mt][na][2]), gelu_t(C[mt][na][3]));
                Hf[mt][kit][2] = f2h2(gelu_t(C[mt][nb][0]), gelu_t(C[mt][nb][1]));
                Hf[mt][kit][3] = f2h2(gelu_t(C[mt][nb][2]), gelu_t(C[mt][nb][3]));
            }
        }

        // ---- re-init C with b2 ----
        #pragma unroll
        for (int nt = 0; nt < 8; nt++) {
            float2 bv = *(const float2*)&b2s[nt * 8 + 2 * rem];
            #pragma unroll
            for (int mt = 0; mt < 2; mt++) {
                C[mt][nt][0] = bv.x; C[mt][nt][1] = bv.y;
                C[mt][nt][2] = bv.x; C[mt][nt][3] = bv.y;
            }
        }

        // ---- GEMM2: H from registers, W2 frags LDS.64 ----
        #pragma unroll
        for (int kit = 0; kit < 4; kit++) {
            uint2 bf[8];
            #pragma unroll
            for (int nt = 0; nt < 8; nt++)
                bf[nt] = *(const uint2*)&W2f[(((kit << 3) + nt) << 6) + (lane << 1)];
            #pragma unroll
            for (int mt = 0; mt < 2; mt++) {
                #pragma unroll
                for (int nt = 0; nt < 8; nt++)
                    mma_f16(C[mt][nt][0], C[mt][nt][1], C[mt][nt][2], C[mt][nt][3],
                            Hf[mt][kit][0], Hf[mt][kit][1],
                            Hf[mt][kit][2], Hf[mt][kit][3],
                            bf[nt].x, bf[nt].y);
            }
        }

        // ---- epilogue2: mask + store (R10 float2 pattern) ----
        #pragma unroll
        for (int mt = 0; mt < 2; mt++) {
            int nm = mt ? n1 : n0;
            bool v0 = grp < nm;
            bool v1 = grp + 8 < nm;
            int r0 = mt * 16 + grp;
            float* orow0 = out_x + ((size_t)s * 32 + r0) * DDIM;
            float* orow1 = orow0 + 8 * DDIM;
            #pragma unroll
            for (int nt = 0; nt < 8; nt++) {
                int col = nt * 8 + 2 * rem;
                float2 lo, hi;
                lo.x = v0 ? C[mt][nt][0] : 0.0f;
                lo.y = v0 ? C[mt][nt][1] : 0.0f;
                hi.x = v1 ? C[mt][nt][2] : 0.0f;
                hi.y = v1 ? C[mt][nt][3] : 0.0f;
                *(float2*)(orow0 + col) = lo;
                *(float2*)(orow1 + col) = hi;
            }
        }
        __syncwarp();
    }
}

// ================= launch =================
extern "C" void kernel_launch(void* const* d_in, const int* in_sizes, int n_in,
                              void* d_out, int out_size) {
    const float* z      = (const float*)d_in[0];
    const float* sp_w1  = (const float*)d_in[1];
    const float* sp_b1  = (const float*)d_in[2];
    const float* sp_w2  = (const float*)d_in[3];
    const float* sp_b2  = (const float*)d_in[4];
    const float* pe_w1  = (const float*)d_in[5];
    const float* pe_b1  = (const float*)d_in[6];
    const float* pe_w2  = (const float*)d_in[7];
    const float* pe_b2  = (const float*)d_in[8];
    const float* dec_w1 = (const float*)d_in[9];
    const float* dec_b1 = (const float*)d_in[10];
    const float* dec_w2 = (const float*)d_in[11];
    const float* dec_b2 = (const float*)d_in[12];

    int B = in_sizes[0] / HDIM;   // 65536

    float* out = (float*)d_out;
    float* out_x     = out;                               // [B,16,64]
    float* out_mask  = out_x + (size_t)B * MAXN * DDIM;   // [B,16]
    float* out_batch = out_mask + (size_t)B * MAXN;       // [B,16]
    float* out_npred = out_batch + (size_t)B * MAXN;      // [B,16]

    static int nsm = 0;
    if (!nsm) {
        cudaDeviceGetAttribute(&nsm, cudaDevAttrMultiProcessorCount, 0);
        if (nsm <= 0) nsm = 148;
        cudaFuncSetAttribute(dec_kernel, cudaFuncAttributeMaxDynamicSharedMemorySize,
                             DEC_SMEM_BYTES);
    }

    sp_kernel<<<B / SP_ROWS, SP_ROWS>>>(z, sp_w1, sp_b1, sp_w2, sp_b2,
                                        out_npred, out_mask, out_batch);

    int nstrips = B / 2;   // 32768 strips of 32 rows
    dec_kernel<<<nsm * 2, DEC_THREADS, DEC_SMEM_BYTES>>>(
        z, dec_w1, dec_b1, dec_w2, dec_b2,
        pe_w1, pe_b1, pe_w2, pe_b2, out_x, nstrips);
}

// round 14
// speedup vs baseline: 1.0811x; 1.0199x over previous
#include <cuda_runtime.h>
#include <cuda_fp16.h>
#include <math.h>
#include <stdint.h>

#define MAXN 16
#define HDIM 64
#define DDIM 64
#define HID 40
#define BMAX 65536

// ---------------- device scratch (no allocations allowed) ----------------
__device__ int g_n[BMAX];                  // per-row argmax

// ---------------- helpers ----------------
// 1-MUFU gelu: hardware tanh.approx.f32
__device__ __forceinline__ float gelu_t(float x) {
    float x2 = x * x;
    float u = x * (0.7978845608f + 0.0356774081f * x2);
    float t;
    asm("tanh.approx.f32 %0, %1;" : "=f"(t) : "f"(u));
    return 0.5f * x * (1.0f + t);
}
// half2 gelu: u = x*(A + B*x^2); y = 0.5x*(1+tanh(u)) all in f16x2
__device__ __forceinline__ uint32_t gelu_h2(uint32_t xb, __half2 A2, __half2 B2,
                                            __half2 H05) {
    __half2 x = *reinterpret_cast<__half2*>(&xb);
    __half2 x2 = __hmul2(x, x);
    __half2 u = __hmul2(x, __hfma2(B2, x2, A2));
    uint32_t ub = *reinterpret_cast<uint32_t*>(&u);
    uint32_t tb;
    asm("tanh.approx.f16x2 %0, %1;" : "=r"(tb) : "r"(ub));
    __half2 t = *reinterpret_cast<__half2*>(&tb);
    __half2 hx = __hmul2(x, H05);
    __half2 y = __hfma2(hx, t, hx);
    return *reinterpret_cast<uint32_t*>(&y);
}
// pack two floats -> half2 bits (lo in low 16 bits)
__device__ __forceinline__ uint32_t f2h2(float lo, float hi) {
    uint32_t r;
    asm("cvt.rn.f16x2.f32 %0, %1, %2;" : "=r"(r) : "f"(hi), "f"(lo));
    return r;
}
__device__ __forceinline__ void mma_f16(float& c0, float& c1, float& c2, float& c3,
                                        uint32_t a0, uint32_t a1, uint32_t a2, uint32_t a3,
                                        uint32_t b0, uint32_t b1) {
    asm volatile(
        "mma.sync.aligned.m16n8k16.row.col.f32.f16.f16.f32 "
        "{%0,%1,%2,%3}, {%4,%5,%6,%7}, {%8,%9}, {%0,%1,%2,%3};"
        : "+f"(c0), "+f"(c1), "+f"(c2), "+f"(c3)
        : "r"(a0), "r"(a1), "r"(a2), "r"(a3), "r"(b0), "r"(b1));
}

// ================= sp: size MLP + argmax + mask/batch/n_pred =================
#define SP_ROWS 128
__global__ void __launch_bounds__(SP_ROWS) sp_kernel(
    const float* __restrict__ z,
    const float* __restrict__ w1, const float* __restrict__ b1,
    const float* __restrict__ w2, const float* __restrict__ b2,
    float* __restrict__ out_npred, float* __restrict__ out_mask,
    float* __restrict__ out_batch) {
    __shared__ float zs[SP_ROWS][65];
    __shared__ float w1s[HDIM * HID];
    __shared__ float w2s[HID * MAXN];
    __shared__ float b1s[HID];
    __shared__ float b2s[MAXN];

    int tid = threadIdx.x;
    int row0 = blockIdx.x * SP_ROWS;

    for (int i = tid; i < HDIM * HID; i += SP_ROWS) w1s[i] = w1[i];
    for (int i = tid; i < HID * MAXN; i += SP_ROWS) w2s[i] = w2[i];
    if (tid < HID)  b1s[tid] = b1[tid];
    if (tid < MAXN) b2s[tid] = b2[tid];
    for (int i = tid; i < SP_ROWS * (HDIM / 4); i += SP_ROWS) {
        int r = i / (HDIM / 4), c4 = i % (HDIM / 4);
        float4 v = ((const float4*)(z + (size_t)(row0 + r) * HDIM))[c4];
        zs[r][c4 * 4 + 0] = v.x;
        zs[r][c4 * 4 + 1] = v.y;
        zs[r][c4 * 4 + 2] = v.z;
        zs[r][c4 * 4 + 3] = v.w;
    }
    __syncthreads();

    int b = row0 + tid;
    float h[HID];
    #pragma unroll
    for (int j4 = 0; j4 < HID / 4; j4++) {
        float4 bv = *(const float4*)&b1s[j4 * 4];
        h[j4 * 4 + 0] = bv.x; h[j4 * 4 + 1] = bv.y;
        h[j4 * 4 + 2] = bv.z; h[j4 * 4 + 3] = bv.w;
    }
    for (int k = 0; k < HDIM; k++) {
        float zk = zs[tid][k];
        const float4* wr = (const float4*)&w1s[k * HID];
        #pragma unroll
        for (int j4 = 0; j4 < HID / 4; j4++) {
            float4 w = wr[j4];
            h[j4 * 4 + 0] += zk * w.x;
            h[j4 * 4 + 1] += zk * w.y;
            h[j4 * 4 + 2] += zk * w.z;
            h[j4 * 4 + 3] += zk * w.w;
        }
    }
    float o[MAXN];
    #pragma unroll
    for (int p4 = 0; p4 < MAXN / 4; p4++) {
        float4 bv = *(const float4*)&b2s[p4 * 4];
        o[p4 * 4 + 0] = bv.x; o[p4 * 4 + 1] = bv.y;
        o[p4 * 4 + 2] = bv.z; o[p4 * 4 + 3] = bv.w;
    }
    #pragma unroll
    for (int j = 0; j < HID; j++) {
        float hj = gelu_t(h[j]);
        const float4* wr = (const float4*)&w2s[j * MAXN];
        #pragma unroll
        for (int p4 = 0; p4 < MAXN / 4; p4++) {
            float4 w = wr[p4];
            o[p4 * 4 + 0] += hj * w.x;
            o[p4 * 4 + 1] += hj * w.y;
            o[p4 * 4 + 2] += hj * w.z;
            o[p4 * 4 + 3] += hj * w.w;
        }
    }
    int n = 0; float best = o[0];
    #pragma unroll
    for (int p = 1; p < MAXN; p++)
        if (o[p] > best) { best = o[p]; n = p; }
    g_n[b] = n;

    size_t base = (size_t)b * MAXN;
    #pragma unroll
    for (int p4 = 0; p4 < MAXN / 4; p4++)
        __stcs((float4*)(out_npred + base + p4 * 4),
               make_float4(o[p4 * 4 + 0], o[p4 * 4 + 1], o[p4 * 4 + 2], o[p4 * 4 + 3]));
    float fb = (float)b;
    #pragma unroll
    for (int p4 = 0; p4 < MAXN / 4; p4++) {
        float4 mv;
        mv.x = (p4 * 4 + 0 < n) ? 1.0f : 0.0f;
        mv.y = (p4 * 4 + 1 < n) ? 1.0f : 0.0f;
        mv.z = (p4 * 4 + 2 < n) ? 1.0f : 0.0f;
        mv.w = (p4 * 4 + 3 < n) ? 1.0f : 0.0f;
        __stcs((float4*)(out_mask + base + p4 * 4), mv);
        __stcs((float4*)(out_batch + base + p4 * 4), make_float4(fb, fb, fb, fb));
    }
}

// ================= dec: R13 config, ONLY epilogue1 switched to half2 gelu ========
#define DEC_THREADS 256
// dynamic smem layout (float indices)
#define SOFF_PE  0                        // [16][68] fp32 = 1088
#define SOFF_ZB  (SOFF_PE + 16 * 68)      // 8 warps * 128 = 1024 (init scratch too)
#define SOFF_B1  (SOFF_ZB + 1024)         // 64
#define SOFF_B2  (SOFF_B1 + 64)           // 64
#define SOFF_W1F (SOFF_B2 + 64)           // 2048 u32: W1 frags [kit*8+nt][lane]
#define SOFF_W2F (SOFF_W1F + 2048)        // 2048 u32
#define DEC_SMEM_FLOATS (SOFF_W2F + 2048)
#define DEC_SMEM_BYTES  (DEC_SMEM_FLOATS * 4)

__global__ void __launch_bounds__(DEC_THREADS, 2) dec_kernel(
    const float* __restrict__ z,
    const float* __restrict__ dw1, const float* __restrict__ db1,
    const float* __restrict__ dw2, const float* __restrict__ db2,
    const float* __restrict__ pw1, const float* __restrict__ pb1,
    const float* __restrict__ pw2, const float* __restrict__ pb2,
    float* __restrict__ out_x, int nstrips) {
    extern __shared__ __align__(16) float smem[];
    float* pe_f = smem + SOFF_PE;          // fp32, pitch 68
    float* zb   = smem + SOFF_ZB;
    float* b1s  = smem + SOFF_B1;
    float* b2s  = smem + SOFF_B2;
    uint32_t* W1f = (uint32_t*)(smem + SOFF_W1F);
    uint32_t* W2f = (uint32_t*)(smem + SOFF_W2F);

    int tid = threadIdx.x;
    int wid = tid >> 5;
    int lane = tid & 31;
    int grp = lane >> 2;                   // 0..7
    int rem = lane & 3;                    // 0..3

    // ---- one-time prologue ----
    {
        float* hid = zb;                   // init scratch (640 <= 1024)
        for (int i = tid; i < MAXN * HID; i += DEC_THREADS)
            hid[i] = gelu_t(pw1[i] + pb1[i % HID]);
        if (tid < 64) { b1s[tid] = db1[tid]; b2s[tid] = db2[tid]; }
        __syncthreads();
        for (int i = tid; i < MAXN * 64; i += DEC_THREADS) {
            int p = i >> 6, d = i & 63;
            float acc = pb2[d];
            #pragma unroll
            for (int j = 0; j < HID; j++) acc += hid[p * HID + j] * pw2[j * 64 + d];
            pe_f[p * 68 + d] = acc;
        }
        __syncthreads();   // hid scratch done before zb reuse
        for (int i = tid; i < 2048; i += DEC_THREADS) {
            int sel = i & 1;
            int lane_ = (i >> 1) & 31;
            int ntk = i >> 6;              // kit*8+nt
            int kit = ntk >> 3, nt = ntk & 7;
            int g_ = lane_ >> 2, r_ = lane_ & 3;
            int k = kit * 16 + 2 * r_ + sel * 8;
            int n = nt * 8 + g_;
            W1f[i] = f2h2(dw1[k * 64 + n], dw1[(k + 1) * 64 + n]);
            W2f[i] = f2h2(dw2[k * 64 + n], dw2[(k + 1) * 64 + n]);
        }
    }
    __syncthreads();

    const __half2 A2  = __float2half2_rn(0.7978845608f);
    const __half2 B2  = __float2half2_rn(0.0356774081f);
    const __half2 H05 = __float2half2_rn(0.5f);

    float* zw = zb + wid * 128;

    int stride = gridDim.x * 8;
    int s = blockIdx.x * 8 + wid;
    if (s >= nstrips) return;

    float4 zcur = ((const float4*)(z + (size_t)s * 128))[lane];
    int ncur0 = g_n[2 * s], ncur1 = g_n[2 * s + 1];

    for (; s < nstrips; s += stride) {
        *(float4*)&zw[lane * 4] = zcur;
        int n0 = ncur0, n1 = ncur1;
        __syncwarp();

        int snext = s + stride;
        if (snext < nstrips) {
            zcur = ((const float4*)(z + (size_t)snext * 128))[lane];
            ncur0 = g_n[2 * snext];
            ncur1 = g_n[2 * snext + 1];
        }

        float C[2][8][4];
        // ---- init C with b1 (bias folded into accumulation) ----
        #pragma unroll
        for (int nt = 0; nt < 8; nt++) {
            float2 bv = *(const float2*)&b1s[nt * 8 + 2 * rem];
            #pragma unroll
            for (int mt = 0; mt < 2; mt++) {
                C[mt][nt][0] = bv.x; C[mt][nt][1] = bv.y;
                C[mt][nt][2] = bv.x; C[mt][nt][3] = bv.y;
            }
        }

        // ---- GEMM1: A built inline (z smem x pe smem), W1 frags LDS.64 ----
        #pragma unroll
        for (int kit = 0; kit < 4; kit++) {
            int kk = kit * 16 + 2 * rem;
            uint2 bf[8];
            #pragma unroll
            for (int nt = 0; nt < 8; nt++)
                bf[nt] = *(const uint2*)&W1f[(((kit << 3) + nt) << 6) + (lane << 1)];
            float2 p0lo = *(const float2*)&pe_f[grp * 68 + kk];
            float2 p1lo = *(const float2*)&pe_f[(grp + 8) * 68 + kk];
            float2 p0hi = *(const float2*)&pe_f[grp * 68 + kk + 8];
            float2 p1hi = *(const float2*)&pe_f[(grp + 8) * 68 + kk + 8];
            #pragma unroll
            for (int mt = 0; mt < 2; mt++) {
                float2 zlo = *(const float2*)&zw[mt * 64 + kk];
                float2 zhi = *(const float2*)&zw[mt * 64 + kk + 8];
                uint32_t a0 = f2h2(zlo.x * p0lo.x, zlo.y * p0lo.y);
                uint32_t a1 = f2h2(zlo.x * p1lo.x, zlo.y * p1lo.y);
                uint32_t a2 = f2h2(zhi.x * p0hi.x, zhi.y * p0hi.y);
                uint32_t a3 = f2h2(zhi.x * p1hi.x, zhi.y * p1hi.y);
                #pragma unroll
                for (int nt = 0; nt < 8; nt++)
                    mma_f16(C[mt][nt][0], C[mt][nt][1], C[mt][nt][2], C[mt][nt][3],
                            a0, a1, a2, a3, bf[nt].x, bf[nt].y);
            }
        }

        // ---- epilogue1 (ONLY change vs R13): half2 gelu -> H fragments ----
        uint32_t Hf[2][4][4];
        #pragma unroll
        for (int mt = 0; mt < 2; mt++) {
            #pragma unroll
            for (int kit = 0; kit < 4; kit++) {
                int na = 2 * kit, nb = 2 * kit + 1;
                Hf[mt][kit][0] = gelu_h2(f2h2(C[mt][na][0], C[mt][na][1]), A2, B2, H05);
                Hf[mt][kit][1] = gelu_h2(f2h2(C[mt][na][2], C[mt][na][3]), A2, B2, H05);
                Hf[mt][kit][2] = gelu_h2(f2h2(C[mt][nb][0], C[mt][nb][1]), A2, B2, H05);
                Hf[mt][kit][3] = gelu_h2(f2h2(C[mt][nb][2], C[mt][nb][3]), A2, B2, H05);
            }
        }

        // ---- re-init C with b2 ----
        #pragma unroll
        for (int nt = 0; nt < 8; nt++) {
            float2 bv = *(const float2*)&b2s[nt * 8 + 2 * rem];
            #pragma unroll
            for (int mt = 0; mt < 2; mt++) {
                C[mt][nt][0] = bv.x; C[mt][nt][1] = bv.y;
                C[mt][nt][2] = bv.x; C[mt][nt][3] = bv.y;
            }
        }

        // ---- GEMM2: H from registers, W2 frags LDS.64 ----
        #pragma unroll
        for (int kit = 0; kit < 4; kit++) {
            uint2 bf[8];
            #pragma unroll
            for (int nt = 0; nt < 8; nt++)
                bf[nt] = *(const uint2*)&W2f[(((kit << 3) + nt) << 6) + (lane << 1)];
            #pragma unroll
            for (int mt = 0; mt < 2; mt++) {
                #pragma unroll
                for (int nt = 0; nt < 8; nt++)
                    mma_f16(C[mt][nt][0], C[mt][nt][1], C[mt][nt][2], C[mt][nt][3],
                            Hf[mt][kit][0], Hf[mt][kit][1],
                            Hf[mt][kit][2], Hf[mt][kit][3],
                            bf[nt].x, bf[nt].y);
            }
        }

        // ---- epilogue2: mask + store (R10/R13 float2 pattern) ----
        #pragma unroll
        for (int mt = 0; mt < 2; mt++) {
            int nm = mt ? n1 : n0;
            bool v0 = grp < nm;
            bool v1 = grp + 8 < nm;
            int r0 = mt * 16 + grp;
            float* orow0 = out_x + ((size_t)s * 32 + r0) * DDIM;
            float* orow1 = orow0 + 8 * DDIM;
            #pragma unroll
            for (int nt = 0; nt < 8; nt++) {
                int col = nt * 8 + 2 * rem;
                float2 lo, hi;
                lo.x = v0 ? C[mt][nt][0] : 0.0f;
                lo.y = v0 ? C[mt][nt][1] : 0.0f;
                hi.x = v1 ? C[mt][nt][2] : 0.0f;
                hi.y = v1 ? C[mt][nt][3] : 0.0f;
                *(float2*)(orow0 + col) = lo;
                *(float2*)(orow1 + col) = hi;
            }
        }
        __syncwarp();
    }
}

// ================= launch =================
extern "C" void kernel_launch(void* const* d_in, const int* in_sizes, int n_in,
                              void* d_out, int out_size) {
    const float* z      = (const float*)d_in[0];
    const float* sp_w1  = (const float*)d_in[1];
    const float* sp_b1  = (const float*)d_in[2];
    const float* sp_w2  = (const float*)d_in[3];
    const float* sp_b2  = (const float*)d_in[4];
    const float* pe_w1  = (const float*)d_in[5];
    const float* pe_b1  = (const float*)d_in[6];
    const float* pe_w2  = (const float*)d_in[7];
    const float* pe_b2  = (const float*)d_in[8];
    const float* dec_w1 = (const float*)d_in[9];
    const float* dec_b1 = (const float*)d_in[10];
    const float* dec_w2 = (const float*)d_in[11];
    const float* dec_b2 = (const float*)d_in[12];

    int B = in_sizes[0] / HDIM;   // 65536

    float* out = (float*)d_out;
    float* out_x     = out;                               // [B,16,64]
    float* out_mask  = out_x + (size_t)B * MAXN * DDIM;   // [B,16]
    float* out_batch = out_mask + (size_t)B * MAXN;       // [B,16]
    float* out_npred = out_batch + (size_t)B * MAXN;      // [B,16]

    static int nsm = 0;
    if (!nsm) {
        cudaDeviceGetAttribute(&nsm, cudaDevAttrMultiProcessorCount, 0);
        if (nsm <= 0) nsm = 148;
        cudaFuncSetAttribute(dec_kernel, cudaFuncAttributeMaxDynamicSharedMemorySize,
                             DEC_SMEM_BYTES);
    }

    sp_kernel<<<B / SP_ROWS, SP_ROWS>>>(z, sp_w1, sp_b1, sp_w2, sp_b2,
                                        out_npred, out_mask, out_batch);

    int nstrips = B / 2;   // 32768 strips of 32 rows
    dec_kernel<<<nsm * 2, DEC_THREADS, DEC_SMEM_BYTES>>>(
        z, dec_w1, dec_b1, dec_w2, dec_b2,
        pe_w1, pe_b1, pe_w2, pe_b2, out_x, nstrips);
}

// round 15
// speedup vs baseline: 1.2435x; 1.1502x over previous
#include <cuda_runtime.h>
#include <cuda_fp16.h>
#include <math.h>
#include <stdint.h>

#define MAXN 16
#define HDIM 64
#define DDIM 64
#define HID 40
#define BMAX 65536

// ---------------- helpers ----------------
// 1-MUFU gelu: hardware tanh.approx.f32
__device__ __forceinline__ float gelu_t(float x) {
    float x2 = x * x;
    float u = x * (0.7978845608f + 0.0356774081f * x2);
    float t;
    asm("tanh.approx.f32 %0, %1;" : "=f"(t) : "f"(u));
    return 0.5f * x * (1.0f + t);
}
// half2 gelu: u = x*(A + B*x^2); y = 0.5x*(1+tanh(u)) all in f16x2
__device__ __forceinline__ uint32_t gelu_h2(uint32_t xb, __half2 A2, __half2 B2,
                                            __half2 H05) {
    __half2 x = *reinterpret_cast<__half2*>(&xb);
    __half2 x2 = __hmul2(x, x);
    __half2 u = __hmul2(x, __hfma2(B2, x2, A2));
    uint32_t ub = *reinterpret_cast<uint32_t*>(&u);
    uint32_t tb;
    asm("tanh.approx.f16x2 %0, %1;" : "=r"(tb) : "r"(ub));
    __half2 t = *reinterpret_cast<__half2*>(&tb);
    __half2 hx = __hmul2(x, H05);
    __half2 y = __hfma2(hx, t, hx);
    return *reinterpret_cast<uint32_t*>(&y);
}
// pack two floats -> half2 bits (lo in low 16 bits)
__device__ __forceinline__ uint32_t f2h2(float lo, float hi) {
    uint32_t r;
    asm("cvt.rn.f16x2.f32 %0, %1, %2;" : "=r"(r) : "f"(hi), "f"(lo));
    return r;
}
__device__ __forceinline__ void mma_f16(float& c0, float& c1, float& c2, float& c3,
                                        uint32_t a0, uint32_t a1, uint32_t a2, uint32_t a3,
                                        uint32_t b0, uint32_t b1) {
    asm volatile(
        "mma.sync.aligned.m16n8k16.row.col.f32.f16.f16.f32 "
        "{%0,%1,%2,%3}, {%4,%5,%6,%7}, {%8,%9}, {%0,%1,%2,%3};"
        : "+f"(c0), "+f"(c1), "+f"(c2), "+f"(c3)
        : "r"(a0), "r"(a1), "r"(a2), "r"(a3), "r"(b0), "r"(b1));
}

// ================= dec: fused sp + decoder, persistent, 2 CTAs/SM =================
#define DEC_THREADS 256
// dynamic smem layout (float indices)
#define SOFF_PE  0                        // [16][68] fp32 = 1088
#define SOFF_ZB  (SOFF_PE + 16 * 68)      // 8 warps * 128 = 1024 (init scratch too)
#define SOFF_B1  (SOFF_ZB + 1024)         // 64
#define SOFF_B2  (SOFF_B1 + 64)           // 64
#define SOFF_W1F (SOFF_B2 + 64)           // 2048 u32: W1 frags [kit*8+nt][lane]
#define SOFF_W2F (SOFF_W1F + 2048)        // 2048 u32
#define DEC_SMEM_FLOATS (SOFF_W2F + 2048)
#define DEC_SMEM_BYTES  (DEC_SMEM_FLOATS * 4)
// sp weights alias over W1F..W2F (4096 floats >= 2560+640+40+16)

__global__ void __launch_bounds__(DEC_THREADS, 2) dec_kernel(
    const float* __restrict__ z,
    const float* __restrict__ dw1, const float* __restrict__ db1,
    const float* __restrict__ dw2, const float* __restrict__ db2,
    const float* __restrict__ pw1, const float* __restrict__ pb1,
    const float* __restrict__ pw2, const float* __restrict__ pb2,
    const float* __restrict__ sw1, const float* __restrict__ sb1,
    const float* __restrict__ sw2, const float* __restrict__ sb2,
    float* __restrict__ out_x, float* __restrict__ out_mask,
    float* __restrict__ out_batch, float* __restrict__ out_npred,
    int nstrips, int per_warp) {
    extern __shared__ __align__(16) float smem[];
    float* pe_f = smem + SOFF_PE;          // fp32, pitch 68
    float* zb   = smem + SOFF_ZB;
    float* b1s  = smem + SOFF_B1;
    float* b2s  = smem + SOFF_B2;
    uint32_t* W1f = (uint32_t*)(smem + SOFF_W1F);
    uint32_t* W2f = (uint32_t*)(smem + SOFF_W2F);

    int tid = threadIdx.x;
    int wid = tid >> 5;
    int lane = tid & 31;
    int grp = lane >> 2;                   // 0..7
    int rem = lane & 3;                    // 0..3

    int warp_global = blockIdx.x * 8 + wid;
    int s0 = warp_global * per_warp;
    int cnt = nstrips - s0;
    if (cnt > per_warp) cnt = per_warp;
    if (cnt < 0) cnt = 0;
    int rowbase = s0 * 2;

    // ================== phase 0+1: size-MLP (exact fp32, lane-per-row) ==========
    int n_mine = 0;
    {
        float* spw1 = (float*)W1f;         // [64][40]
        float* spw2 = spw1 + 2560;         // [40][16]
        float* spb1 = spw2 + 640;          // 40
        float* spb2 = spb1 + 40;           // 16
        for (int i = tid; i < HDIM * HID; i += DEC_THREADS) spw1[i] = sw1[i];
        for (int i = tid; i < HID * MAXN; i += DEC_THREADS) spw2[i] = sw2[i];
        if (tid < HID)  spb1[tid] = sb1[tid];
        if (tid < MAXN) spb2[tid] = sb2[tid];
        __syncthreads();

        int nrows = 2 * cnt;
        if (lane < nrows) {
            int row = rowbase + lane;
            float h[HID];
            #pragma unroll
            for (int j4 = 0; j4 < HID / 4; j4++) {
                float4 bv = *(const float4*)&spb1[j4 * 4];
                h[j4 * 4 + 0] = bv.x; h[j4 * 4 + 1] = bv.y;
                h[j4 * 4 + 2] = bv.z; h[j4 * 4 + 3] = bv.w;
            }
            const float4* zrow = (const float4*)(z + (size_t)row * HDIM);
            #pragma unroll 4
            for (int k4 = 0; k4 < 16; k4++) {
                float4 zv = zrow[k4];
                #pragma unroll
                for (int kk = 0; kk < 4; kk++) {
                    float zk = (kk == 0) ? zv.x : (kk == 1) ? zv.y
                             : (kk == 2) ? zv.z : zv.w;
                    const float4* wr = (const float4*)&spw1[(k4 * 4 + kk) * HID];
                    #pragma unroll
                    for (int j4 = 0; j4 < HID / 4; j4++) {
                        float4 w = wr[j4];
                        h[j4 * 4 + 0] += zk * w.x;
                        h[j4 * 4 + 1] += zk * w.y;
                        h[j4 * 4 + 2] += zk * w.z;
                        h[j4 * 4 + 3] += zk * w.w;
                    }
                }
            }
            float o[MAXN];
            #pragma unroll
            for (int p4 = 0; p4 < MAXN / 4; p4++) {
                float4 bv = *(const float4*)&spb2[p4 * 4];
                o[p4 * 4 + 0] = bv.x; o[p4 * 4 + 1] = bv.y;
                o[p4 * 4 + 2] = bv.z; o[p4 * 4 + 3] = bv.w;
            }
            #pragma unroll
            for (int j = 0; j < HID; j++) {
                float hj = gelu_t(h[j]);
                const float4* wr = (const float4*)&spw2[j * MAXN];
                #pragma unroll
                for (int p4 = 0; p4 < MAXN / 4; p4++) {
                    float4 w = wr[p4];
                    o[p4 * 4 + 0] += hj * w.x;
                    o[p4 * 4 + 1] += hj * w.y;
                    o[p4 * 4 + 2] += hj * w.z;
                    o[p4 * 4 + 3] += hj * w.w;
                }
            }
            int n = 0; float best = o[0];
            #pragma unroll
            for (int p = 1; p < MAXN; p++)
                if (o[p] > best) { best = o[p]; n = p; }
            n_mine = n;

            size_t base = (size_t)row * MAXN;
            #pragma unroll
            for (int p4 = 0; p4 < MAXN / 4; p4++)
                __stcs((float4*)(out_npred + base + p4 * 4),
                       make_float4(o[p4 * 4 + 0], o[p4 * 4 + 1],
                                   o[p4 * 4 + 2], o[p4 * 4 + 3]));
            float fb = (float)row;
            #pragma unroll
            for (int p4 = 0; p4 < MAXN / 4; p4++) {
                float4 mv;
                mv.x = (p4 * 4 + 0 < n) ? 1.0f : 0.0f;
                mv.y = (p4 * 4 + 1 < n) ? 1.0f : 0.0f;
                mv.z = (p4 * 4 + 2 < n) ? 1.0f : 0.0f;
                mv.w = (p4 * 4 + 3 < n) ? 1.0f : 0.0f;
                __stcs((float4*)(out_mask + base + p4 * 4), mv);
                __stcs((float4*)(out_batch + base + p4 * 4),
                       make_float4(fb, fb, fb, fb));
            }
        }
        __syncthreads();   // sp done before W-frag region is overwritten
    }

    // ================== phase 2: decoder prologue (pe, biases, W frags) =========
    {
        float* hid = zb;                   // init scratch (640 <= 1024)
        for (int i = tid; i < MAXN * HID; i += DEC_THREADS)
            hid[i] = gelu_t(pw1[i] + pb1[i % HID]);
        if (tid < 64) { b1s[tid] = db1[tid]; b2s[tid] = db2[tid]; }
        __syncthreads();
        for (int i = tid; i < MAXN * 64; i += DEC_THREADS) {
            int p = i >> 6, d = i & 63;
            float acc = pb2[d];
            #pragma unroll
            for (int j = 0; j < HID; j++) acc += hid[p * HID + j] * pw2[j * 64 + d];
            pe_f[p * 68 + d] = acc;
        }
        __syncthreads();   // hid scratch done before zb reuse
        for (int i = tid; i < 2048; i += DEC_THREADS) {
            int sel = i & 1;
            int lane_ = (i >> 1) & 31;
            int ntk = i >> 6;              // kit*8+nt
            int kit = ntk >> 3, nt = ntk & 7;
            int g_ = lane_ >> 2, r_ = lane_ & 3;
            int k = kit * 16 + 2 * r_ + sel * 8;
            int n = nt * 8 + g_;
            W1f[i] = f2h2(dw1[k * 64 + n], dw1[(k + 1) * 64 + n]);
            W2f[i] = f2h2(dw2[k * 64 + n], dw2[(k + 1) * 64 + n]);
        }
    }
    __syncthreads();

    if (cnt == 0) return;

    const __half2 A2  = __float2half2_rn(0.7978845608f);
    const __half2 B2  = __float2half2_rn(0.0356774081f);
    const __half2 H05 = __float2half2_rn(0.5f);

    float* zw = zb + wid * 128;

    // ================== phase 3: decoder main loop (contiguous strips) ==========
    float4 zcur = ((const float4*)(z + (size_t)s0 * 128))[lane];

    for (int si = 0; si < cnt; si++) {
        int s = s0 + si;
        *(float4*)&zw[lane * 4] = zcur;
        int n0 = __shfl_sync(0xffffffffu, n_mine, 2 * si);
        int n1 = __shfl_sync(0xffffffffu, n_mine, 2 * si + 1);
        __syncwarp();

        if (si + 1 < cnt)
            zcur = ((const float4*)(z + (size_t)(s + 1) * 128))[lane];

        float C[2][8][4];
        // ---- init C with b1 (bias folded into accumulation) ----
        #pragma unroll
        for (int nt = 0; nt < 8; nt++) {
            float2 bv = *(const float2*)&b1s[nt * 8 + 2 * rem];
            #pragma unroll
            for (int mt = 0; mt < 2; mt++) {
                C[mt][nt][0] = bv.x; C[mt][nt][1] = bv.y;
                C[mt][nt][2] = bv.x; C[mt][nt][3] = bv.y;
            }
        }

        // ---- GEMM1: A built inline (z smem x pe smem), W1 frags LDS.64 ----
        #pragma unroll
        for (int kit = 0; kit < 4; kit++) {
            int kk = kit * 16 + 2 * rem;
            uint2 bf[8];
            #pragma unroll
            for (int nt = 0; nt < 8; nt++)
                bf[nt] = *(const uint2*)&W1f[(((kit << 3) + nt) << 6) + (lane << 1)];
            float2 p0lo = *(const float2*)&pe_f[grp * 68 + kk];
            float2 p1lo = *(const float2*)&pe_f[(grp + 8) * 68 + kk];
            float2 p0hi = *(const float2*)&pe_f[grp * 68 + kk + 8];
            float2 p1hi = *(const float2*)&pe_f[(grp + 8) * 68 + kk + 8];
            #pragma unroll
            for (int mt = 0; mt < 2; mt++) {
                float2 zlo = *(const float2*)&zw[mt * 64 + kk];
                float2 zhi = *(const float2*)&zw[mt * 64 + kk + 8];
                uint32_t a0 = f2h2(zlo.x * p0lo.x, zlo.y * p0lo.y);
                uint32_t a1 = f2h2(zlo.x * p1lo.x, zlo.y * p1lo.y);
                uint32_t a2 = f2h2(zhi.x * p0hi.x, zhi.y * p0hi.y);
                uint32_t a3 = f2h2(zhi.x * p1hi.x, zhi.y * p1hi.y);
                #pragma unroll
                for (int nt = 0; nt < 8; nt++)
                    mma_f16(C[mt][nt][0], C[mt][nt][1], C[mt][nt][2], C[mt][nt][3],
                            a0, a1, a2, a3, bf[nt].x, bf[nt].y);
            }
        }

        // ---- epilogue1: half2 gelu -> H fragments in registers ----
        uint32_t Hf[2][4][4];
        #pragma unroll
        for (int mt = 0; mt < 2; mt++) {
            #pragma unroll
            for (int kit = 0; kit < 4; kit++) {
                int na = 2 * kit, nb = 2 * kit + 1;
                Hf[mt][kit][0] = gelu_h2(f2h2(C[mt][na][0], C[mt][na][1]), A2, B2, H05);
                Hf[mt][kit][1] = gelu_h2(f2h2(C[mt][na][2], C[mt][na][3]), A2, B2, H05);
                Hf[mt][kit][2] = gelu_h2(f2h2(C[mt][nb][0], C[mt][nb][1]), A2, B2, H05);
                Hf[mt][kit][3] = gelu_h2(f2h2(C[mt][nb][2], C[mt][nb][3]), A2, B2, H05);
            }
        }

        // ---- re-init C with b2 ----
        #pragma unroll
        for (int nt = 0; nt < 8; nt++) {
            float2 bv = *(const float2*)&b2s[nt * 8 + 2 * rem];
            #pragma unroll
            for (int mt = 0; mt < 2; mt++) {
                C[mt][nt][0] = bv.x; C[mt][nt][1] = bv.y;
                C[mt][nt][2] = bv.x; C[mt][nt][3] = bv.y;
            }
        }

        // ---- GEMM2: H from registers, W2 frags LDS.64 ----
        #pragma unroll
        for (int kit = 0; kit < 4; kit++) {
            uint2 bf[8];
            #pragma unroll
            for (int nt = 0; nt < 8; nt++)
                bf[nt] = *(const uint2*)&W2f[(((kit << 3) + nt) << 6) + (lane << 1)];
            #pragma unroll
            for (int mt = 0; mt < 2; mt++) {
                #pragma unroll
                for (int nt = 0; nt < 8; nt++)
                    mma_f16(C[mt][nt][0], C[mt][nt][1], C[mt][nt][2], C[mt][nt][3],
                            Hf[mt][kit][0], Hf[mt][kit][1],
                            Hf[mt][kit][2], Hf[mt][kit][3],
                            bf[nt].x, bf[nt].y);
            }
        }

        // ---- epilogue2: mask + store (float2 pattern) ----
        #pragma unroll
        for (int mt = 0; mt < 2; mt++) {
            int nm = mt ? n1 : n0;
            bool v0 = grp < nm;
            bool v1 = grp + 8 < nm;
            int r0 = mt * 16 + grp;
            float* orow0 = out_x + ((size_t)s * 32 + r0) * DDIM;
            float* orow1 = orow0 + 8 * DDIM;
            #pragma unroll
            for (int nt = 0; nt < 8; nt++) {
                int col = nt * 8 + 2 * rem;
                float2 lo, hi;
                lo.x = v0 ? C[mt][nt][0] : 0.0f;
                lo.y = v0 ? C[mt][nt][1] : 0.0f;
                hi.x = v1 ? C[mt][nt][2] : 0.0f;
                hi.y = v1 ? C[mt][nt][3] : 0.0f;
                *(float2*)(orow0 + col) = lo;
                *(float2*)(orow1 + col) = hi;
            }
        }
        __syncwarp();
    }
}

// ================= launch =================
extern "C" void kernel_launch(void* const* d_in, const int* in_sizes, int n_in,
                              void* d_out, int out_size) {
    const float* z      = (const float*)d_in[0];
    const float* sp_w1  = (const float*)d_in[1];
    const float* sp_b1  = (const float*)d_in[2];
    const float* sp_w2  = (const float*)d_in[3];
    const float* sp_b2  = (const float*)d_in[4];
    const float* pe_w1  = (const float*)d_in[5];
    const float* pe_b1  = (const float*)d_in[6];
    const float* pe_w2  = (const float*)d_in[7];
    const float* pe_b2  = (const float*)d_in[8];
    const float* dec_w1 = (const float*)d_in[9];
    const float* dec_b1 = (const float*)d_in[10];
    const float* dec_w2 = (const float*)d_in[11];
    const float* dec_b2 = (const float*)d_in[12];

    int B = in_sizes[0] / HDIM;   // 65536

    float* out = (float*)d_out;
    float* out_x     = out;                               // [B,16,64]
    float* out_mask  = out_x + (size_t)B * MAXN * DDIM;   // [B,16]
    float* out_batch = out_mask + (size_t)B * MAXN;       // [B,16]
    float* out_npred = out_batch + (size_t)B * MAXN;      // [B,16]

    static int nsm = 0;
    if (!nsm) {
        cudaDeviceGetAttribute(&nsm, cudaDevAttrMultiProcessorCount, 0);
        if (nsm <= 0) nsm = 148;
        cudaFuncSetAttribute(dec_kernel, cudaFuncAttributeMaxDynamicSharedMemorySize,
                             DEC_SMEM_BYTES);
    }

    int nstrips = B / 2;             // 32768 strips of 32 rows
    int gridB = nsm * 2;
    int nwarps = gridB * 8;
    int per_warp = (nstrips + nwarps - 1) / nwarps;   // <= 14 (28 rows <= 32 lanes)

    dec_kernel<<<gridB, DEC_THREADS, DEC_SMEM_BYTES>>>(
        z, dec_w1, dec_b1, dec_w2, dec_b2,
        pe_w1, pe_b1, pe_w2, pe_b2,
        sp_w1, sp_b1, sp_w2, sp_b2,
        out_x, out_mask, out_batch, out_npred, nstrips, per_warp);
}

// round 16
// speedup vs baseline: 1.2579x; 1.0116x over previous
#include <cuda_runtime.h>
#include <cuda_fp16.h>
#include <math.h>
#include <stdint.h>

#define MAXN 16
#define HDIM 64
#define DDIM 64
#define HID 40
#define BMAX 65536

// ---------------- helpers ----------------
// 1-MUFU gelu: hardware tanh.approx.f32
__device__ __forceinline__ float gelu_t(float x) {
    float x2 = x * x;
    float u = x * (0.7978845608f + 0.0356774081f * x2);
    float t;
    asm("tanh.approx.f32 %0, %1;" : "=f"(t) : "f"(u));
    return 0.5f * x * (1.0f + t);
}
// half2 "2x gelu": G = x + x*tanh(u)  (pair with 0.5-scaled W2; exact fold)
__device__ __forceinline__ uint32_t gelu2_h2(uint32_t xb, __half2 A2, __half2 B2) {
    __half2 x = *reinterpret_cast<__half2*>(&xb);
    __half2 x2 = __hmul2(x, x);
    __half2 u = __hmul2(x, __hfma2(B2, x2, A2));
    uint32_t ub = *reinterpret_cast<uint32_t*>(&u);
    uint32_t tb;
    asm("tanh.approx.f16x2 %0, %1;" : "=r"(tb) : "r"(ub));
    __half2 t = *reinterpret_cast<__half2*>(&tb);
    __half2 y = __hfma2(x, t, x);
    return *reinterpret_cast<uint32_t*>(&y);
}
// pack two floats -> half2 bits (lo in low 16 bits)
__device__ __forceinline__ uint32_t f2h2(float lo, float hi) {
    uint32_t r;
    asm("cvt.rn.f16x2.f32 %0, %1, %2;" : "=r"(r) : "f"(hi), "f"(lo));
    return r;
}
__device__ __forceinline__ void mma_f16(float& c0, float& c1, float& c2, float& c3,
                                        uint32_t a0, uint32_t a1, uint32_t a2, uint32_t a3,
                                        uint32_t b0, uint32_t b1) {
    asm volatile(
        "mma.sync.aligned.m16n8k16.row.col.f32.f16.f16.f32 "
        "{%0,%1,%2,%3}, {%4,%5,%6,%7}, {%8,%9}, {%0,%1,%2,%3};"
        : "+f"(c0), "+f"(c1), "+f"(c2), "+f"(c3)
        : "r"(a0), "r"(a1), "r"(a2), "r"(a3), "r"(b0), "r"(b1));
}

// ================= dec: fused sp + decoder, persistent, 2 CTAs/SM =================
#define DEC_THREADS 256
// dynamic smem layout (float indices)
#define SOFF_PEQ 0                        // 1024: pe frags [kit][lane] 2x float4
#define SOFF_ZB  (SOFF_PEQ + 1024)        // 1024: hid scratch / per-warp z (128 ea)
#define SOFF_B1Q (SOFF_ZB + 1024)         // 64: b1 frag pairs [ntp][rem] float4
#define SOFF_B2Q (SOFF_B1Q + 64)          // 64
#define SOFF_W1F (SOFF_B2Q + 64)          // 2048 u32: W1 frag pairs [kit][ntp][lane] uint4
#define SOFF_W2F (SOFF_W1F + 2048)        // 2048 u32 (0.5-scaled)
#define DEC_SMEM_FLOATS (SOFF_W2F + 2048)
#define DEC_SMEM_BYTES  (DEC_SMEM_FLOATS * 4)
// sp weights alias over W1F..W2F (4096 floats >= 2560+640+40+16)

__global__ void __launch_bounds__(DEC_THREADS, 2) dec_kernel(
    const float* __restrict__ z,
    const float* __restrict__ dw1, const float* __restrict__ db1,
    const float* __restrict__ dw2, const float* __restrict__ db2,
    const float* __restrict__ pw1, const float* __restrict__ pb1,
    const float* __restrict__ pw2, const float* __restrict__ pb2,
    const float* __restrict__ sw1, const float* __restrict__ sb1,
    const float* __restrict__ sw2, const float* __restrict__ sb2,
    float* __restrict__ out_x, float* __restrict__ out_mask,
    float* __restrict__ out_batch, float* __restrict__ out_npred,
    int nstrips, int per_warp) {
    extern __shared__ __align__(16) float smem[];
    float* zb   = smem + SOFF_ZB;
    const float4* peq4 = (const float4*)(smem + SOFF_PEQ);
    const float4* b1q4 = (const float4*)(smem + SOFF_B1Q);
    const float4* b2q4 = (const float4*)(smem + SOFF_B2Q);
    uint32_t* W1f = (uint32_t*)(smem + SOFF_W1F);
    uint32_t* W2f = (uint32_t*)(smem + SOFF_W2F);
    const uint4* W1q4 = (const uint4*)W1f;
    const uint4* W2q4 = (const uint4*)W2f;

    int tid = threadIdx.x;
    int wid = tid >> 5;
    int lane = tid & 31;
    int grp = lane >> 2;                   // 0..7
    int rem = lane & 3;                    // 0..3

    int warp_global = blockIdx.x * 8 + wid;
    int s0 = warp_global * per_warp;
    int cnt = nstrips - s0;
    if (cnt > per_warp) cnt = per_warp;
    if (cnt < 0) cnt = 0;

    // ================== phase 0: size-MLP (exact fp32, lane-per-row) ============
    int n_mine = 0;
    {
        float* spw1 = (float*)W1f;         // [64][40]
        float* spw2 = spw1 + 2560;         // [40][16]
        float* spb1 = spw2 + 640;          // 40
        float* spb2 = spb1 + 40;           // 16
        for (int i = tid; i < HDIM * HID; i += DEC_THREADS) spw1[i] = sw1[i];
        for (int i = tid; i < HID * MAXN; i += DEC_THREADS) spw2[i] = sw2[i];
        if (tid < HID)  spb1[tid] = sb1[tid];
        if (tid < MAXN) spb2[tid] = sb2[tid];
        __syncthreads();

        int nrows = 2 * cnt;
        if (lane < nrows) {
            int row = s0 * 2 + lane;
            float h[HID];
            #pragma unroll
            for (int j4 = 0; j4 < HID / 4; j4++) {
                float4 bv = *(const float4*)&spb1[j4 * 4];
                h[j4 * 4 + 0] = bv.x; h[j4 * 4 + 1] = bv.y;
                h[j4 * 4 + 2] = bv.z; h[j4 * 4 + 3] = bv.w;
            }
            const float4* zrow = (const float4*)(z + (size_t)row * HDIM);
            #pragma unroll 8
            for (int k4 = 0; k4 < 16; k4++) {
                float4 zv = zrow[k4];
                #pragma unroll
                for (int kk = 0; kk < 4; kk++) {
                    float zk = (kk == 0) ? zv.x : (kk == 1) ? zv.y
                             : (kk == 2) ? zv.z : zv.w;
                    const float4* wr = (const float4*)&spw1[(k4 * 4 + kk) * HID];
                    #pragma unroll
                    for (int j4 = 0; j4 < HID / 4; j4++) {
                        float4 w = wr[j4];
                        h[j4 * 4 + 0] += zk * w.x;
                        h[j4 * 4 + 1] += zk * w.y;
                        h[j4 * 4 + 2] += zk * w.z;
                        h[j4 * 4 + 3] += zk * w.w;
                    }
                }
            }
            float o[MAXN];
            #pragma unroll
            for (int p4 = 0; p4 < MAXN / 4; p4++) {
                float4 bv = *(const float4*)&spb2[p4 * 4];
                o[p4 * 4 + 0] = bv.x; o[p4 * 4 + 1] = bv.y;
                o[p4 * 4 + 2] = bv.z; o[p4 * 4 + 3] = bv.w;
            }
            #pragma unroll
            for (int j = 0; j < HID; j++) {
                float hj = gelu_t(h[j]);
                const float4* wr = (const float4*)&spw2[j * MAXN];
                #pragma unroll
                for (int p4 = 0; p4 < MAXN / 4; p4++) {
                    float4 w = wr[p4];
                    o[p4 * 4 + 0] += hj * w.x;
                    o[p4 * 4 + 1] += hj * w.y;
                    o[p4 * 4 + 2] += hj * w.z;
                    o[p4 * 4 + 3] += hj * w.w;
                }
            }
            int n = 0; float best = o[0];
            #pragma unroll
            for (int p = 1; p < MAXN; p++)
                if (o[p] > best) { best = o[p]; n = p; }
            n_mine = n;

            size_t base = (size_t)row * MAXN;
            #pragma unroll
            for (int p4 = 0; p4 < MAXN / 4; p4++)
                __stcs((float4*)(out_npred + base + p4 * 4),
                       make_float4(o[p4 * 4 + 0], o[p4 * 4 + 1],
                                   o[p4 * 4 + 2], o[p4 * 4 + 3]));
            float fb = (float)row;
            #pragma unroll
            for (int p4 = 0; p4 < MAXN / 4; p4++) {
                float4 mv;
                mv.x = (p4 * 4 + 0 < n) ? 1.0f : 0.0f;
                mv.y = (p4 * 4 + 1 < n) ? 1.0f : 0.0f;
                mv.z = (p4 * 4 + 2 < n) ? 1.0f : 0.0f;
                mv.w = (p4 * 4 + 3 < n) ? 1.0f : 0.0f;
                __stcs((float4*)(out_mask + base + p4 * 4), mv);
                __stcs((float4*)(out_batch + base + p4 * 4),
                       make_float4(fb, fb, fb, fb));
            }
        }
        __syncthreads();   // sp done before W-frag region is overwritten
    }

    // ================== phase 1: decoder prologue =================================
    {
        float* hid = zb;                   // pe-MLP hidden (640 <= 1024)
        for (int i = tid; i < MAXN * HID; i += DEC_THREADS)
            hid[i] = gelu_t(pw1[i] + pb1[i % HID]);
        __syncthreads();

        // peq: pe fragment quads built directly from hidden (covers all 16x64 once)
        float* peq = smem + SOFF_PEQ;
        for (int i = tid; i < 1024; i += DEC_THREADS) {
            int kit = i >> 8;
            int lane_ = (i >> 3) & 31;
            int e = i & 7;
            int g_ = lane_ >> 2, r_ = lane_ & 3;
            int row = g_ + ((e & 4) ? 8 : 0);
            int col = kit * 16 + 2 * r_ + ((e & 2) ? 8 : 0) + (e & 1);
            float acc = pb2[col];
            #pragma unroll
            for (int j = 0; j < HID; j++) acc += hid[row * HID + j] * pw2[j * 64 + col];
            peq[i] = acc;
        }
        // bias fragment quads: [(ntp*4+rem_)] = (b[nt,2r],b[nt,2r+1],b[nt+1,2r],b[nt+1,2r+1])
        if (tid < 128) {
            int which = tid >> 6;          // 0: b1, 1: b2
            int i = tid & 63;
            int ntp = i >> 4, rem_ = (i >> 2) & 3, e = i & 3;
            int nt = 2 * ntp + (e >> 1);
            int col = nt * 8 + 2 * rem_ + (e & 1);
            smem[(which ? SOFF_B2Q : SOFF_B1Q) + i] = which ? db2[col] : db1[col];
        }
        // W fragment quads: i -> (kit, ntp, lane_, w); w = {nt_even:sel0,sel1, nt_odd:sel0,sel1}
        for (int i = tid; i < 2048; i += DEC_THREADS) {
            int kit = i >> 9;
            int ntp = (i >> 7) & 3;
            int lane_ = (i >> 2) & 31;
            int w = i & 3;
            int nt = 2 * ntp + (w >> 1);
            int sel = w & 1;
            int g_ = lane_ >> 2, r_ = lane_ & 3;
            int k = kit * 16 + 2 * r_ + sel * 8;
            int n = nt * 8 + g_;
            W1f[i] = f2h2(dw1[k * 64 + n], dw1[(k + 1) * 64 + n]);
            W2f[i] = f2h2(0.5f * dw2[k * 64 + n], 0.5f * dw2[(k + 1) * 64 + n]);
        }
    }
    __syncthreads();

    if (cnt == 0) return;

    const __half2 A2 = __float2half2_rn(0.7978845608f);
    const __half2 B2 = __float2half2_rn(0.0356774081f);

    float* zw = zb + wid * 128;

    // ================== phase 2: decoder main loop ================================
    float4 zcur = ((const float4*)(z + (size_t)s0 * 128))[lane];

    for (int si = 0; si < cnt; si++) {
        int s = s0 + si;
        *(float4*)&zw[lane * 4] = zcur;
        int n0 = __shfl_sync(0xffffffffu, n_mine, 2 * si);
        int n1 = __shfl_sync(0xffffffffu, n_mine, 2 * si + 1);
        __syncwarp();

        if (si + 1 < cnt)
            zcur = ((const float4*)(z + (size_t)(s + 1) * 128))[lane];

        float C[2][8][4];
        // ---- init C with b1 fragment quads ----
        #pragma unroll
        for (int ntp = 0; ntp < 4; ntp++) {
            float4 bv = b1q4[ntp * 4 + rem];
            #pragma unroll
            for (int mt = 0; mt < 2; mt++) {
                C[mt][2 * ntp][0] = bv.x; C[mt][2 * ntp][1] = bv.y;
                C[mt][2 * ntp][2] = bv.x; C[mt][2 * ntp][3] = bv.y;
                C[mt][2 * ntp + 1][0] = bv.z; C[mt][2 * ntp + 1][1] = bv.w;
                C[mt][2 * ntp + 1][2] = bv.z; C[mt][2 * ntp + 1][3] = bv.w;
            }
        }

        // ---- GEMM1: A inline (z smem x peq), W1 quad LDS.128 ----
        #pragma unroll
        for (int kit = 0; kit < 4; kit++) {
            int kk = kit * 16 + 2 * rem;
            uint4 bq[4];
            #pragma unroll
            for (int ntp = 0; ntp < 4; ntp++)
                bq[ntp] = W1q4[(kit * 4 + ntp) * 32 + lane];
            float4 Q0 = peq4[(kit * 32 + lane) * 2 + 0];   // p rows (grp): lo pair, hi pair
            float4 Q1 = peq4[(kit * 32 + lane) * 2 + 1];   // p rows (grp+8)
            #pragma unroll
            for (int mt = 0; mt < 2; mt++) {
                float2 zlo = *(const float2*)&zw[mt * 64 + kk];
                float2 zhi = *(const float2*)&zw[mt * 64 + kk + 8];
                uint32_t a0 = f2h2(zlo.x * Q0.x, zlo.y * Q0.y);
                uint32_t a1 = f2h2(zlo.x * Q1.x, zlo.y * Q1.y);
                uint32_t a2 = f2h2(zhi.x * Q0.z, zhi.y * Q0.w);
                uint32_t a3 = f2h2(zhi.x * Q1.z, zhi.y * Q1.w);
                #pragma unroll
                for (int ntp = 0; ntp < 4; ntp++) {
                    mma_f16(C[mt][2 * ntp][0], C[mt][2 * ntp][1],
                            C[mt][2 * ntp][2], C[mt][2 * ntp][3],
                            a0, a1, a2, a3, bq[ntp].x, bq[ntp].y);
                    mma_f16(C[mt][2 * ntp + 1][0], C[mt][2 * ntp + 1][1],
                            C[mt][2 * ntp + 1][2], C[mt][2 * ntp + 1][3],
                            a0, a1, a2, a3, bq[ntp].z, bq[ntp].w);
                }
            }
        }

        // ---- epilogue1: half2 2x-gelu -> H fragments in registers ----
        uint32_t Hf[2][4][4];
        #pragma unroll
        for (int mt = 0; mt < 2; mt++) {
            #pragma unroll
            for (int kit = 0; kit < 4; kit++) {
                int na = 2 * kit, nb = 2 * kit + 1;
                Hf[mt][kit][0] = gelu2_h2(f2h2(C[mt][na][0], C[mt][na][1]), A2, B2);
                Hf[mt][kit][1] = gelu2_h2(f2h2(C[mt][na][2], C[mt][na][3]), A2, B2);
                Hf[mt][kit][2] = gelu2_h2(f2h2(C[mt][nb][0], C[mt][nb][1]), A2, B2);
                Hf[mt][kit][3] = gelu2_h2(f2h2(C[mt][nb][2], C[mt][nb][3]), A2, B2);
            }
        }

        // ---- re-init C with b2 fragment quads ----
        #pragma unroll
        for (int ntp = 0; ntp < 4; ntp++) {
            float4 bv = b2q4[ntp * 4 + rem];
            #pragma unroll
            for (int mt = 0; mt < 2; mt++) {
                C[mt][2 * ntp][0] = bv.x; C[mt][2 * ntp][1] = bv.y;
                C[mt][2 * ntp][2] = bv.x; C[mt][2 * ntp][3] = bv.y;
                C[mt][2 * ntp + 1][0] = bv.z; C[mt][2 * ntp + 1][1] = bv.w;
                C[mt][2 * ntp + 1][2] = bv.z; C[mt][2 * ntp + 1][3] = bv.w;
            }
        }

        // ---- GEMM2: H (=2*gelu) regs, 0.5*W2 quad LDS.128 ----
        #pragma unroll
        for (int kit = 0; kit < 4; kit++) {
            uint4 bq[4];
            #pragma unroll
            for (int ntp = 0; ntp < 4; ntp++)
                bq[ntp] = W2q4[(kit * 4 + ntp) * 32 + lane];
            #pragma unroll
            for (int mt = 0; mt < 2; mt++) {
                #pragma unroll
                for (int ntp = 0; ntp < 4; ntp++) {
                    mma_f16(C[mt][2 * ntp][0], C[mt][2 * ntp][1],
                            C[mt][2 * ntp][2], C[mt][2 * ntp][3],
                            Hf[mt][kit][0], Hf[mt][kit][1],
                            Hf[mt][kit][2], Hf[mt][kit][3],
                            bq[ntp].x, bq[ntp].y);
                    mma_f16(C[mt][2 * ntp + 1][0], C[mt][2 * ntp + 1][1],
                            C[mt][2 * ntp + 1][2], C[mt][2 * ntp + 1][3],
                            Hf[mt][kit][0], Hf[mt][kit][1],
                            Hf[mt][kit][2], Hf[mt][kit][3],
                            bq[ntp].z, bq[ntp].w);
                }
            }
        }

        // ---- epilogue2: mask + store (float2 pattern) ----
        #pragma unroll
        for (int mt = 0; mt < 2; mt++) {
            int nm = mt ? n1 : n0;
            bool v0 = grp < nm;
            bool v1 = grp + 8 < nm;
            int r0 = mt * 16 + grp;
            float* orow0 = out_x + ((size_t)s * 32 + r0) * DDIM;
            float* orow1 = orow0 + 8 * DDIM;
            #pragma unroll
            for (int nt = 0; nt < 8; nt++) {
                int col = nt * 8 + 2 * rem;
                float2 lo, hi;
                lo.x = v0 ? C[mt][nt][0] : 0.0f;
                lo.y = v0 ? C[mt][nt][1] : 0.0f;
                hi.x = v1 ? C[mt][nt][2] : 0.0f;
                hi.y = v1 ? C[mt][nt][3] : 0.0f;
                *(float2*)(orow0 + col) = lo;
                *(float2*)(orow1 + col) = hi;
            }
        }
        __syncwarp();
    }
}

// ================= launch =================
extern "C" void kernel_launch(void* const* d_in, const int* in_sizes, int n_in,
                              void* d_out, int out_size) {
    const float* z      = (const float*)d_in[0];
    const float* sp_w1  = (const float*)d_in[1];
    const float* sp_b1  = (const float*)d_in[2];
    const float* sp_w2  = (const float*)d_in[3];
    const float* sp_b2  = (const float*)d_in[4];
    const float* pe_w1  = (const float*)d_in[5];
    const float* pe_b1  = (const float*)d_in[6];
    const float* pe_w2  = (const float*)d_in[7];
    const float* pe_b2  = (const float*)d_in[8];
    const float* dec_w1 = (const float*)d_in[9];
    const float* dec_b1 = (const float*)d_in[10];
    const float* dec_w2 = (const float*)d_in[11];
    const float* dec_b2 = (const float*)d_in[12];

    int B = in_sizes[0] / HDIM;   // 65536

    float* out = (float*)d_out;
    float* out_x     = out;                               // [B,16,64]
    float* out_mask  = out_x + (size_t)B * MAXN * DDIM;   // [B,16]
    float* out_batch = out_mask + (size_t)B * MAXN;       // [B,16]
    float* out_npred = out_batch + (size_t)B * MAXN;      // [B,16]

    static int nsm = 0;
    if (!nsm) {
        cudaDeviceGetAttribute(&nsm, cudaDevAttrMultiProcessorCount, 0);
        if (nsm <= 0) nsm = 148;
        cudaFuncSetAttribute(dec_kernel, cudaFuncAttributeMaxDynamicSharedMemorySize,
                             DEC_SMEM_BYTES);
    }

    int nstrips = B / 2;             // 32768 strips of 32 rows
    int gridB = nsm * 2;
    int nwarps = gridB * 8;
    int per_warp = (nstrips + nwarps - 1) / nwarps;   // <= 14 (28 rows <= 32 lanes)

    dec_kernel<<<gridB, DEC_THREADS, DEC_SMEM_BYTES>>>(
        z, dec_w1, dec_b1, dec_w2, dec_b2,
        pe_w1, pe_b1, pe_w2, pe_b2,
        sp_w1, sp_b1, sp_w2, sp_b2,
        out_x, out_mask, out_batch, out_npred, nstrips, per_warp);
}

// round 17
// speedup vs baseline: 1.2643x; 1.0051x over previous
#include <cuda_runtime.h>
#include <cuda_fp16.h>
#include <math.h>
#include <stdint.h>

#define MAXN 16
#define HDIM 64
#define DDIM 64
#define HID 40
#define BMAX 65536

// ---------------- helpers ----------------
// 1-MUFU gelu: hardware tanh.approx.f32
__device__ __forceinline__ float gelu_t(float x) {
    float x2 = x * x;
    float u = x * (0.7978845608f + 0.0356774081f * x2);
    float t;
    asm("tanh.approx.f32 %0, %1;" : "=f"(t) : "f"(u));
    return 0.5f * x * (1.0f + t);
}
// half2 "2x gelu": G = x + x*tanh(u)  (pair with 0.5-scaled W2; exact fold)
__device__ __forceinline__ uint32_t gelu2_h2(uint32_t xb, __half2 A2, __half2 B2) {
    __half2 x = *reinterpret_cast<__half2*>(&xb);
    __half2 x2 = __hmul2(x, x);
    __half2 u = __hmul2(x, __hfma2(B2, x2, A2));
    uint32_t ub = *reinterpret_cast<uint32_t*>(&u);
    uint32_t tb;
    asm("tanh.approx.f16x2 %0, %1;" : "=r"(tb) : "r"(ub));
    __half2 t = *reinterpret_cast<__half2*>(&tb);
    __half2 y = __hfma2(x, t, x);
    return *reinterpret_cast<uint32_t*>(&y);
}
// pack two floats -> half2 bits (lo in low 16 bits)
__device__ __forceinline__ uint32_t f2h2(float lo, float hi) {
    uint32_t r;
    asm("cvt.rn.f16x2.f32 %0, %1, %2;" : "=r"(r) : "f"(hi), "f"(lo));
    return r;
}
__device__ __forceinline__ void mma_f16(float& c0, float& c1, float& c2, float& c3,
                                        uint32_t a0, uint32_t a1, uint32_t a2, uint32_t a3,
                                        uint32_t b0, uint32_t b1) {
    asm volatile(
        "mma.sync.aligned.m16n8k16.row.col.f32.f16.f16.f32 "
        "{%0,%1,%2,%3}, {%4,%5,%6,%7}, {%8,%9}, {%0,%1,%2,%3};"
        : "+f"(c0), "+f"(c1), "+f"(c2), "+f"(c3)
        : "r"(a0), "r"(a1), "r"(a2), "r"(a3), "r"(b0), "r"(b1));
}
// packed fp32x2 FMA (exact IEEE fp32 on both halves)
#define FMA2(acc, a2, b2v) \
    asm("fma.rn.f32x2 %0, %1, %2, %0;" : "+l"(acc) : "l"(a2), "l"(b2v))
__device__ __forceinline__ unsigned long long splat2(float a) {
    unsigned long long r;
    unsigned int u = __float_as_uint(a);
    asm("mov.b64 %0, {%1, %1};" : "=l"(r) : "r"(u));
    return r;
}
__device__ __forceinline__ void unpack2(unsigned long long v, float& lo, float& hi) {
    unsigned int u0, u1;
    asm("mov.b64 {%0, %1}, %2;" : "=r"(u0), "=r"(u1) : "l"(v));
    lo = __uint_as_float(u0);
    hi = __uint_as_float(u1);
}

// ================= dec: fused sp + decoder, persistent, 2 CTAs/SM =================
#define DEC_THREADS 256
// dynamic smem layout (float indices)
#define SOFF_PEQ 0                        // 1024: pe frags [kit][lane] 2x float4
#define SOFF_ZB  (SOFF_PEQ + 1024)        // 1024: hid scratch / per-warp z (128 ea)
#define SOFF_B1Q (SOFF_ZB + 1024)         // 64: b1 frag pairs [ntp][rem] float4
#define SOFF_B2Q (SOFF_B1Q + 64)          // 64
#define SOFF_W1F (SOFF_B2Q + 64)          // 2048 u32: W1 frag pairs [kit][ntp][lane] uint4
#define SOFF_W2F (SOFF_W1F + 2048)        // 2048 u32 (0.5-scaled)
#define DEC_SMEM_FLOATS (SOFF_W2F + 2048)
#define DEC_SMEM_BYTES  (DEC_SMEM_FLOATS * 4)
// sp weights alias over W1F..W2F (4096 floats >= 2560+640+40+16)

__global__ void __launch_bounds__(DEC_THREADS, 2) dec_kernel(
    const float* __restrict__ z,
    const float* __restrict__ dw1, const float* __restrict__ db1,
    const float* __restrict__ dw2, const float* __restrict__ db2,
    const float* __restrict__ pw1, const float* __restrict__ pb1,
    const float* __restrict__ pw2, const float* __restrict__ pb2,
    const float* __restrict__ sw1, const float* __restrict__ sb1,
    const float* __restrict__ sw2, const float* __restrict__ sb2,
    float* __restrict__ out_x, float* __restrict__ out_mask,
    float* __restrict__ out_batch, float* __restrict__ out_npred,
    int nstrips, int per_warp) {
    extern __shared__ __align__(16) float smem[];
    float* zb   = smem + SOFF_ZB;
    const float4* peq4 = (const float4*)(smem + SOFF_PEQ);
    const float4* b1q4 = (const float4*)(smem + SOFF_B1Q);
    const float4* b2q4 = (const float4*)(smem + SOFF_B2Q);
    uint32_t* W1f = (uint32_t*)(smem + SOFF_W1F);
    uint32_t* W2f = (uint32_t*)(smem + SOFF_W2F);
    const uint4* W1q4 = (const uint4*)W1f;
    const uint4* W2q4 = (const uint4*)W2f;

    int tid = threadIdx.x;
    int wid = tid >> 5;
    int lane = tid & 31;
    int grp = lane >> 2;                   // 0..7
    int rem = lane & 3;                    // 0..3

    int warp_global = blockIdx.x * 8 + wid;
    int s0 = warp_global * per_warp;
    int cnt = nstrips - s0;
    if (cnt > per_warp) cnt = per_warp;
    if (cnt < 0) cnt = 0;

    // ====== phase 0: size-MLP (exact fp32, lane-per-row, f32x2-packed) ==========
    int n_mine = 0;
    {
        float* spw1 = (float*)W1f;         // [64][40]
        float* spw2 = spw1 + 2560;         // [40][16]
        float* spb1 = spw2 + 640;          // 40
        float* spb2 = spb1 + 40;           // 16
        for (int i = tid; i < HDIM * HID; i += DEC_THREADS) spw1[i] = sw1[i];
        for (int i = tid; i < HID * MAXN; i += DEC_THREADS) spw2[i] = sw2[i];
        if (tid < HID)  spb1[tid] = sb1[tid];
        if (tid < MAXN) spb2[tid] = sb2[tid];
        __syncthreads();

        int nrows = 2 * cnt;
        if (lane < nrows) {
            int row = s0 * 2 + lane;
            // layer 1: h (40) as 20 packed f32x2
            unsigned long long h2[20];
            {
                const unsigned long long* b1p = (const unsigned long long*)spb1;
                #pragma unroll
                for (int j2 = 0; j2 < 20; j2++) h2[j2] = b1p[j2];
            }
            const float4* zrow = (const float4*)(z + (size_t)row * HDIM);
            #pragma unroll 8
            for (int k4 = 0; k4 < 16; k4++) {
                float4 zv = zrow[k4];
                #pragma unroll
                for (int kk = 0; kk < 4; kk++) {
                    float zk = (kk == 0) ? zv.x : (kk == 1) ? zv.y
                             : (kk == 2) ? zv.z : zv.w;
                    unsigned long long zk2 = splat2(zk);
                    const float4* wr = (const float4*)&spw1[(k4 * 4 + kk) * HID];
                    #pragma unroll
                    for (int j4 = 0; j4 < 10; j4++) {
                        float4 w = wr[j4];
                        ulonglong2 wp = *reinterpret_cast<ulonglong2*>(&w);
                        FMA2(h2[j4 * 2 + 0], zk2, wp.x);
                        FMA2(h2[j4 * 2 + 1], zk2, wp.y);
                    }
                }
            }
            // layer 2: o (16) as 8 packed f32x2; per-element j-order preserved
            unsigned long long o2[8];
            {
                const unsigned long long* b2p = (const unsigned long long*)spb2;
                #pragma unroll
                for (int p2 = 0; p2 < 8; p2++) o2[p2] = b2p[p2];
            }
            #pragma unroll
            for (int j2 = 0; j2 < 20; j2++) {
                float hlo, hhi;
                unpack2(h2[j2], hlo, hhi);
                unsigned long long g0 = splat2(gelu_t(hlo));
                unsigned long long g1 = splat2(gelu_t(hhi));
                const float4* wr0 = (const float4*)&spw2[(2 * j2) * MAXN];
                const float4* wr1 = (const float4*)&spw2[(2 * j2 + 1) * MAXN];
                #pragma unroll
                for (int p4 = 0; p4 < 4; p4++) {
                    float4 w0 = wr0[p4];
                    ulonglong2 w0p = *reinterpret_cast<ulonglong2*>(&w0);
                    float4 w1 = wr1[p4];
                    ulonglong2 w1p = *reinterpret_cast<ulonglong2*>(&w1);
                    FMA2(o2[p4 * 2 + 0], g0, w0p.x);
                    FMA2(o2[p4 * 2 + 1], g0, w0p.y);
                    FMA2(o2[p4 * 2 + 0], g1, w1p.x);
                    FMA2(o2[p4 * 2 + 1], g1, w1p.y);
                }
            }
            float o[MAXN];
            #pragma unroll
            for (int p2 = 0; p2 < 8; p2++) unpack2(o2[p2], o[2 * p2], o[2 * p2 + 1]);

            int n = 0; float best = o[0];
            #pragma unroll
            for (int p = 1; p < MAXN; p++)
                if (o[p] > best) { best = o[p]; n = p; }
            n_mine = n;

            size_t base = (size_t)row * MAXN;
            #pragma unroll
            for (int p4 = 0; p4 < MAXN / 4; p4++)
                __stcs((float4*)(out_npred + base + p4 * 4),
                       make_float4(o[p4 * 4 + 0], o[p4 * 4 + 1],
                                   o[p4 * 4 + 2], o[p4 * 4 + 3]));
            float fb = (float)row;
            #pragma unroll
            for (int p4 = 0; p4 < MAXN / 4; p4++) {
                float4 mv;
                mv.x = (p4 * 4 + 0 < n) ? 1.0f : 0.0f;
                mv.y = (p4 * 4 + 1 < n) ? 1.0f : 0.0f;
                mv.z = (p4 * 4 + 2 < n) ? 1.0f : 0.0f;
                mv.w = (p4 * 4 + 3 < n) ? 1.0f : 0.0f;
                __stcs((float4*)(out_mask + base + p4 * 4), mv);
                __stcs((float4*)(out_batch + base + p4 * 4),
                       make_float4(fb, fb, fb, fb));
            }
        }
        __syncthreads();   // sp done before W-frag region is overwritten
    }

    // ================== phase 1: decoder prologue =================================
    {
        float* hid = zb;                   // pe-MLP hidden (640 <= 1024)
        for (int i = tid; i < MAXN * HID; i += DEC_THREADS)
            hid[i] = gelu_t(pw1[i] + pb1[i % HID]);
        __syncthreads();

        // peq: pe fragment quads built directly from hidden (covers all 16x64 once)
        float* peq = smem + SOFF_PEQ;
        for (int i = tid; i < 1024; i += DEC_THREADS) {
            int kit = i >> 8;
            int lane_ = (i >> 3) & 31;
            int e = i & 7;
            int g_ = lane_ >> 2, r_ = lane_ & 3;
            int row = g_ + ((e & 4) ? 8 : 0);
            int col = kit * 16 + 2 * r_ + ((e & 2) ? 8 : 0) + (e & 1);
            float acc = pb2[col];
            #pragma unroll
            for (int j = 0; j < HID; j++) acc += hid[row * HID + j] * pw2[j * 64 + col];
            peq[i] = acc;
        }
        // bias fragment quads
        if (tid < 128) {
            int which = tid >> 6;          // 0: b1, 1: b2
            int i = tid & 63;
            int ntp = i >> 4, rem_ = (i >> 2) & 3, e = i & 3;
            int nt = 2 * ntp + (e >> 1);
            int col = nt * 8 + 2 * rem_ + (e & 1);
            smem[(which ? SOFF_B2Q : SOFF_B1Q) + i] = which ? db2[col] : db1[col];
        }
        // W fragment quads
        for (int i = tid; i < 2048; i += DEC_THREADS) {
            int kit = i >> 9;
            int ntp = (i >> 7) & 3;
            int lane_ = (i >> 2) & 31;
            int w = i & 3;
            int nt = 2 * ntp + (w >> 1);
            int sel = w & 1;
            int g_ = lane_ >> 2, r_ = lane_ & 3;
            int k = kit * 16 + 2 * r_ + sel * 8;
            int n = nt * 8 + g_;
            W1f[i] = f2h2(dw1[k * 64 + n], dw1[(k + 1) * 64 + n]);
            W2f[i] = f2h2(0.5f * dw2[k * 64 + n], 0.5f * dw2[(k + 1) * 64 + n]);
        }
    }
    __syncthreads();

    if (cnt == 0) return;

    const __half2 A2 = __float2half2_rn(0.7978845608f);
    const __half2 B2 = __float2half2_rn(0.0356774081f);

    float* zw = zb + wid * 128;

    // ================== phase 2: decoder main loop ================================
    float4 zcur = ((const float4*)(z + (size_t)s0 * 128))[lane];

    for (int si = 0; si < cnt; si++) {
        int s = s0 + si;
        *(float4*)&zw[lane * 4] = zcur;
        int n0 = __shfl_sync(0xffffffffu, n_mine, 2 * si);
        int n1 = __shfl_sync(0xffffffffu, n_mine, 2 * si + 1);
        __syncwarp();

        if (si + 1 < cnt)
            zcur = ((const float4*)(z + (size_t)(s + 1) * 128))[lane];

        float C[2][8][4];
        // ---- init C with b1 fragment quads ----
        #pragma unroll
        for (int ntp = 0; ntp < 4; ntp++) {
            float4 bv = b1q4[ntp * 4 + rem];
            #pragma unroll
            for (int mt = 0; mt < 2; mt++) {
                C[mt][2 * ntp][0] = bv.x; C[mt][2 * ntp][1] = bv.y;
                C[mt][2 * ntp][2] = bv.x; C[mt][2 * ntp][3] = bv.y;
                C[mt][2 * ntp + 1][0] = bv.z; C[mt][2 * ntp + 1][1] = bv.w;
                C[mt][2 * ntp + 1][2] = bv.z; C[mt][2 * ntp + 1][3] = bv.w;
            }
        }

        // ---- GEMM1: A inline (z smem x peq), W1 quad LDS.128 ----
        #pragma unroll
        for (int kit = 0; kit < 4; kit++) {
            int kk = kit * 16 + 2 * rem;
            uint4 bq[4];
            #pragma unroll
            for (int ntp = 0; ntp < 4; ntp++)
                bq[ntp] = W1q4[(kit * 4 + ntp) * 32 + lane];
            float4 Q0 = peq4[(kit * 32 + lane) * 2 + 0];
            float4 Q1 = peq4[(kit * 32 + lane) * 2 + 1];
            #pragma unroll
            for (int mt = 0; mt < 2; mt++) {
                float2 zlo = *(const float2*)&zw[mt * 64 + kk];
                float2 zhi = *(const float2*)&zw[mt * 64 + kk + 8];
                uint32_t a0 = f2h2(zlo.x * Q0.x, zlo.y * Q0.y);
                uint32_t a1 = f2h2(zlo.x * Q1.x, zlo.y * Q1.y);
                uint32_t a2 = f2h2(zhi.x * Q0.z, zhi.y * Q0.w);
                uint32_t a3 = f2h2(zhi.x * Q1.z, zhi.y * Q1.w);
                #pragma unroll
                for (int ntp = 0; ntp < 4; ntp++) {
                    mma_f16(C[mt][2 * ntp][0], C[mt][2 * ntp][1],
                            C[mt][2 * ntp][2], C[mt][2 * ntp][3],
                            a0, a1, a2, a3, bq[ntp].x, bq[ntp].y);
                    mma_f16(C[mt][2 * ntp + 1][0], C[mt][2 * ntp + 1][1],
                            C[mt][2 * ntp + 1][2], C[mt][2 * ntp + 1][3],
                            a0, a1, a2, a3, bq[ntp].z, bq[ntp].w);
                }
            }
        }

        // ---- epilogue1: half2 2x-gelu -> H fragments in registers ----
        uint32_t Hf[2][4][4];
        #pragma unroll
        for (int mt = 0; mt < 2; mt++) {
            #pragma unroll
            for (int kit = 0; kit < 4; kit++) {
                int na = 2 * kit, nb = 2 * kit + 1;
                Hf[mt][kit][0] = gelu2_h2(f2h2(C[mt][na][0], C[mt][na][1]), A2, B2);
                Hf[mt][kit][1] = gelu2_h2(f2h2(C[mt][na][2], C[mt][na][3]), A2, B2);
                Hf[mt][kit][2] = gelu2_h2(f2h2(C[mt][nb][0], C[mt][nb][1]), A2, B2);
                Hf[mt][kit][3] = gelu2_h2(f2h2(C[mt][nb][2], C[mt][nb][3]), A2, B2);
            }
        }

        // ---- re-init C with b2 fragment quads ----
        #pragma unroll
        for (int ntp = 0; ntp < 4; ntp++) {
            float4 bv = b2q4[ntp * 4 + rem];
            #pragma unroll
            for (int mt = 0; mt < 2; mt++) {
                C[mt][2 * ntp][0] = bv.x; C[mt][2 * ntp][1] = bv.y;
                C[mt][2 * ntp][2] = bv.x; C[mt][2 * ntp][3] = bv.y;
                C[mt][2 * ntp + 1][0] = bv.z; C[mt][2 * ntp + 1][1] = bv.w;
                C[mt][2 * ntp + 1][2] = bv.z; C[mt][2 * ntp + 1][3] = bv.w;
            }
        }

        // ---- GEMM2: H (=2*gelu) regs, 0.5*W2 quad LDS.128 ----
        #pragma unroll
        for (int kit = 0; kit < 4; kit++) {
            uint4 bq[4];
            #pragma unroll
            for (int ntp = 0; ntp < 4; ntp++)
                bq[ntp] = W2q4[(kit * 4 + ntp) * 32 + lane];
            #pragma unroll
            for (int mt = 0; mt < 2; mt++) {
                #pragma unroll
                for (int ntp = 0; ntp < 4; ntp++) {
                    mma_f16(C[mt][2 * ntp][0], C[mt][2 * ntp][1],
                            C[mt][2 * ntp][2], C[mt][2 * ntp][3],
                            Hf[mt][kit][0], Hf[mt][kit][1],
                            Hf[mt][kit][2], Hf[mt][kit][3],
                            bq[ntp].x, bq[ntp].y);
                    mma_f16(C[mt][2 * ntp + 1][0], C[mt][2 * ntp + 1][1],
                            C[mt][2 * ntp + 1][2], C[mt][2 * ntp + 1][3],
                            Hf[mt][kit][0], Hf[mt][kit][1],
                            Hf[mt][kit][2], Hf[mt][kit][3],
                            bq[ntp].z, bq[ntp].w);
                }
            }
        }

        // ---- epilogue2: mask + store (float2 pattern) ----
        #pragma unroll
        for (int mt = 0; mt < 2; mt++) {
            int nm = mt ? n1 : n0;
            bool v0 = grp < nm;
            bool v1 = grp + 8 < nm;
            int r0 = mt * 16 + grp;
            float* orow0 = out_x + ((size_t)s * 32 + r0) * DDIM;
            float* orow1 = orow0 + 8 * DDIM;
            #pragma unroll
            for (int nt = 0; nt < 8; nt++) {
                int col = nt * 8 + 2 * rem;
                float2 lo, hi;
                lo.x = v0 ? C[mt][nt][0] : 0.0f;
                lo.y = v0 ? C[mt][nt][1] : 0.0f;
                hi.x = v1 ? C[mt][nt][2] : 0.0f;
                hi.y = v1 ? C[mt][nt][3] : 0.0f;
                *(float2*)(orow0 + col) = lo;
                *(float2*)(orow1 + col) = hi;
            }
        }
        __syncwarp();
    }
}

// ================= launch =================
extern "C" void kernel_launch(void* const* d_in, const int* in_sizes, int n_in,
                              void* d_out, int out_size) {
    const float* z      = (const float*)d_in[0];
    const float* sp_w1  = (const float*)d_in[1];
    const float* sp_b1  = (const float*)d_in[2];
    const float* sp_w2  = (const float*)d_in[3];
    const float* sp_b2  = (const float*)d_in[4];
    const float* pe_w1  = (const float*)d_in[5];
    const float* pe_b1  = (const float*)d_in[6];
    const float* pe_w2  = (const float*)d_in[7];
    const float* pe_b2  = (const float*)d_in[8];
    const float* dec_w1 = (const float*)d_in[9];
    const float* dec_b1 = (const float*)d_in[10];
    const float* dec_w2 = (const float*)d_in[11];
    const float* dec_b2 = (const float*)d_in[12];

    int B = in_sizes[0] / HDIM;   // 65536

    float* out = (float*)d_out;
    float* out_x     = out;                               // [B,16,64]
    float* out_mask  = out_x + (size_t)B * MAXN * DDIM;   // [B,16]
    float* out_batch = out_mask + (size_t)B * MAXN;       // [B,16]
    float* out_npred = out_batch + (size_t)B * MAXN;      // [B,16]

    static int nsm = 0;
    if (!nsm) {
        cudaDeviceGetAttribute(&nsm, cudaDevAttrMultiProcessorCount, 0);
        if (nsm <= 0) nsm = 148;
        cudaFuncSetAttribute(dec_kernel, cudaFuncAttributeMaxDynamicSharedMemorySize,
                             DEC_SMEM_BYTES);
    }

    int nstrips = B / 2;             // 32768 strips of 32 rows
    int gridB = nsm * 2;
    int nwarps = gridB * 8;
    int per_warp = (nstrips + nwarps - 1) / nwarps;   // <= 14 (28 rows <= 32 lanes)

    dec_kernel<<<gridB, DEC_THREADS, DEC_SMEM_BYTES>>>(
        z, dec_w1, dec_b1, dec_w2, dec_b2,
        pe_w1, pe_b1, pe_w2, pe_b2,
        sp_w1, sp_b1, sp_w2, sp_b2,
        out_x, out_mask, out_batch, out_npred, nstrips, per_warp);
}